// round 2
// baseline (speedup 1.0000x reference)
#include <cuda_runtime.h>
#include <math.h>

#define NCH 4
#define NN 20000
#define NE 320000
#define NT 16
#define HID 32

// edge-type metadata: 4 spatial (c->c) then 12 inter-channel (s!=d)
__constant__ int c_src[16] = {0,1,2,3, 0,0,0, 1,1,1, 2,2,2, 3,3,3};
__constant__ int c_dst[16] = {0,1,2,3, 1,2,3, 0,2,3, 0,1,3, 0,1,2};
__constant__ int c_in[4][4] = {{0,7,10,13},{1,4,11,14},{2,5,8,15},{3,6,9,12}};

// scratch (static device globals; no allocation)
__device__ int    g_count[NT*NN];
__device__ int    g_off[NT*(NN+1)];
__device__ int    g_cur[NT*NN];
__device__ int    g_col[NT*NE];
__device__ float4 g_za[NT*NN];          // layer1 per-(type,dst,head) scalar aggregate
__device__ float  g_y[NCH*NN*HID];      // layer1 output (post relu)
__device__ float4 g_s2[NT*NN];          // layer2 src scores per head
__device__ float4 g_d2[NT*NN];          // layer2 dst scores per head
__device__ float4 g_As2[NT*HID];        // W2^T @ att_src2 folded: [t][f][h]
__device__ float4 g_Ad2[NT*HID];
__device__ float4 g_SA[NT];             // layer1 folded score weights [t][h]
__device__ float4 g_DA[NT];
__device__ float  g_out2[NCH*NN*HID];   // layer2 accumulator across edge types

__device__ __forceinline__ float lrelu(float v){ return v > 0.f ? v : 0.2f*v; }

// ---------------- zero counters & accumulators ----------------
__global__ void zero_kernel(){
    int i = blockIdx.x*blockDim.x + threadIdx.x;
    int stride = gridDim.x*blockDim.x;
    for (int k = i; k < NT*NN; k += stride) g_count[k] = 0;
    for (int k = i; k < NCH*NN*HID; k += stride) g_out2[k] = 0.f;
}

// ---------------- CSR build: count ----------------
__global__ void count_kernel(const int* __restrict__ edges){
    int i = blockIdx.x*blockDim.x + threadIdx.x;
    if (i >= NT*NE) return;
    int t = i / NE, e = i % NE;
    int dst = edges[t*2*NE + NE + e];
    atomicAdd(&g_count[t*NN + dst], 1);
}

// ---------------- CSR build: exclusive scan per type ----------------
__global__ void scan_kernel(){
    __shared__ int sdata[1024];
    __shared__ int carry;
    int t = blockIdx.x;
    int tid = threadIdx.x;
    if (tid == 0){ carry = 0; g_off[t*(NN+1)] = 0; }
    __syncthreads();
    for (int base = 0; base < NN; base += 1024){
        int c0 = carry;
        int i = base + tid;
        int v = (i < NN) ? g_count[t*NN + i] : 0;
        sdata[tid] = v;
        __syncthreads();
        #pragma unroll
        for (int ofs = 1; ofs < 1024; ofs <<= 1){
            int add = (tid >= ofs) ? sdata[tid-ofs] : 0;
            __syncthreads();
            sdata[tid] += add;
            __syncthreads();
        }
        int incl = sdata[tid] + c0;
        if (i < NN){
            g_off[t*(NN+1) + i + 1] = incl;
            g_cur[t*NN + i] = incl - v;   // exclusive offset = cursor start
        }
        __syncthreads();
        if (tid == 1023) carry = incl;
        __syncthreads();
    }
}

// ---------------- CSR build: fill ----------------
__global__ void fill_kernel(const int* __restrict__ edges){
    int i = blockIdx.x*blockDim.x + threadIdx.x;
    if (i >= NT*NE) return;
    int t = i / NE, e = i % NE;
    int src = edges[t*2*NE + e];
    int dst = edges[t*2*NE + NE + e];
    int pos = atomicAdd(&g_cur[t*NN + dst], 1);
    g_col[t*NE + pos] = src;
}

// ---------------- fold attention weights ----------------
// As2[t][f][h] = sum_c W2[t][f][h*32+c] * att_src2[t][h][c]; similarly Ad2.
// SA[t][h] = sum_c W1[t][0][h*32+c] * att_src1[t][h][c]; similarly DA.
__global__ void param_kernel(const float* __restrict__ W1, const float* __restrict__ as1,
                             const float* __restrict__ ad1,
                             const float* __restrict__ W2, const float* __restrict__ as2,
                             const float* __restrict__ ad2){
    int i = blockIdx.x*blockDim.x + threadIdx.x;
    if (i >= NT*HID*4) return;
    int t = i / (HID*4);
    int r = i % (HID*4);
    int f = r / 4, h = r % 4;
    float sa = 0.f, sd = 0.f;
    const float* wrow = W2 + (t*HID + f)*128 + h*32;
    const float* arow = as2 + (t*4 + h)*32;
    const float* drow = ad2 + (t*4 + h)*32;
    #pragma unroll
    for (int c = 0; c < 32; c++){ sa += wrow[c]*arow[c]; sd += wrow[c]*drow[c]; }
    ((float*)g_As2)[(t*HID + f)*4 + h] = sa;
    ((float*)g_Ad2)[(t*HID + f)*4 + h] = sd;
    if (f == 0){
        float s1 = 0.f, d1 = 0.f;
        const float* w1 = W1 + t*128 + h*32;
        const float* a1 = as1 + (t*4 + h)*32;
        const float* dd1 = ad1 + (t*4 + h)*32;
        #pragma unroll
        for (int c = 0; c < 32; c++){ s1 += w1[c]*a1[c]; d1 += w1[c]*dd1[c]; }
        ((float*)g_SA)[t*4 + h] = s1;
        ((float*)g_DA)[t*4 + h] = d1;
    }
}

// ---------------- layer-1 edge aggregation: thread per (type,dst) ----------------
// za[t][dst][h] = softmax-weighted sum of x_src over incoming edges.
__global__ void l1_edge_kernel(const float* __restrict__ x){
    int i = blockIdx.x*blockDim.x + threadIdx.x;
    if (i >= NT*NN) return;
    int t = i / NN, n = i % NN;
    float4 SAv = g_SA[t];
    float4 DAv = g_DA[t];
    float SA[4] = {SAv.x, SAv.y, SAv.z, SAv.w};
    float DA[4] = {DAv.x, DAv.y, DAv.z, DAv.w};
    float xd = x[c_dst[t]*NN + n];
    float dsc[4];
    #pragma unroll
    for (int h = 0; h < 4; h++) dsc[h] = xd * DA[h];
    const float* xs = x + c_src[t]*NN;
    const int* col = g_col + t*NE;
    int beg = g_off[t*(NN+1) + n];
    int end = g_off[t*(NN+1) + n + 1];
    float m[4], den[4], acc[4];
    #pragma unroll
    for (int h = 0; h < 4; h++){ m[h] = -1e30f; den[h] = 0.f; acc[h] = 0.f; }
    for (int j = beg; j < end; j++){
        int s = col[j];
        float xv = xs[s];
        #pragma unroll
        for (int h = 0; h < 4; h++){
            float e = lrelu(xv*SA[h] + dsc[h]);
            if (e > m[h]){
                float cr = __expf(m[h] - e);
                den[h] = den[h]*cr + 1.f;
                acc[h] = acc[h]*cr + xv;
                m[h] = e;
            } else {
                float p = __expf(e - m[h]);
                den[h] += p;
                acc[h] += p*xv;
            }
        }
    }
    float4 z;
    z.x = den[0] > 0.f ? acc[0]/den[0] : 0.f;
    z.y = den[1] > 0.f ? acc[1]/den[1] : 0.f;
    z.z = den[2] > 0.f ? acc[2]/den[2] : 0.f;
    z.w = den[3] > 0.f ? acc[3]/den[3] : 0.f;
    g_za[t*NN + n] = z;
}

// ---------------- layer-1 combine: rank-1 expansion + hetero mean + relu ----------------
__global__ void l1_combine_kernel(const float* __restrict__ W1, const float* __restrict__ b1){
    int i = blockIdx.x*blockDim.x + threadIdx.x;
    if (i >= NCH*NN*HID) return;
    int c = i / (NN*HID);
    int r = i % (NN*HID);
    int n = r / HID, j = r % HID;
    float v = 0.f;
    #pragma unroll
    for (int k = 0; k < 4; k++){
        int t = c_in[c][k];
        float4 za = g_za[t*NN + n];
        const float* w = W1 + t*128;
        float o = za.x*w[j] + za.y*w[32+j] + za.z*w[64+j] + za.w*w[96+j];
        v += o*0.25f + b1[t*HID + j];
    }
    v *= 0.25f;                       // hetero mean over 4 incoming types
    g_y[c*NN*HID + n*HID + j] = v > 0.f ? v : 0.f;
}

// ---------------- layer-2 score tables ----------------
__global__ void l2_score_kernel(){
    int i = blockIdx.x*blockDim.x + threadIdx.x;
    if (i >= NT*NN) return;
    int t = i / NN, n = i % NN;
    const float* ys = g_y + c_src[t]*NN*HID + n*HID;
    const float* yd = g_y + c_dst[t]*NN*HID + n*HID;
    float s[4] = {0,0,0,0}, d[4] = {0,0,0,0};
    #pragma unroll
    for (int f = 0; f < HID; f++){
        float4 a = g_As2[t*HID + f];
        float4 b = g_Ad2[t*HID + f];
        float yv = ys[f], ydv = yd[f];
        s[0] += yv*a.x; s[1] += yv*a.y; s[2] += yv*a.z; s[3] += yv*a.w;
        d[0] += ydv*b.x; d[1] += ydv*b.y; d[2] += ydv*b.z; d[3] += ydv*b.w;
    }
    g_s2[t*NN + n] = make_float4(s[0], s[1], s[2], s[3]);
    g_d2[t*NN + n] = make_float4(d[0], d[1], d[2], d[3]);
}

// ---------------- layer-2 edge gather + fused in-warp GEMM ----------------
// warp per dst node; lane = feature f. z[h,f] accumulated in registers with
// online softmax (exactly one __expf per edge per head, warp-uniform branch).
// Then out[h,c] = sum_f z[h,f]*W2[f,h*32+c] via shfl-broadcast GEMM from SMEM.
__global__ void __launch_bounds__(256) l2_edge_kernel(const float* __restrict__ W2,
                                                      const float* __restrict__ b2){
    int t = blockIdx.y;
    __shared__ float Ws[HID*128];
    for (int i = threadIdx.x; i < HID*128; i += 256) Ws[i] = W2[t*HID*128 + i];
    __syncthreads();
    int warp = threadIdx.x >> 5, lane = threadIdx.x & 31;
    int n = blockIdx.x*8 + warp;
    if (n >= NN) return;
    const float* ysrc = g_y + c_src[t]*NN*HID;
    float4 d2v = g_d2[t*NN + n];
    float dsc[4] = {d2v.x, d2v.y, d2v.z, d2v.w};
    const int* col = g_col + t*NE;
    int beg = g_off[t*(NN+1) + n];
    int end = g_off[t*(NN+1) + n + 1];
    float m[4], den[4], acc[4];
    #pragma unroll
    for (int h = 0; h < 4; h++){ m[h] = -1e30f; den[h] = 0.f; acc[h] = 0.f; }
    for (int j = beg; j < end; j++){
        int s = col[j];                         // uniform across warp
        float4 s2v = g_s2[t*NN + s];            // broadcast load
        float sv[4] = {s2v.x, s2v.y, s2v.z, s2v.w};
        float yv = ysrc[s*HID + lane];          // coalesced 128B gather
        #pragma unroll
        for (int h = 0; h < 4; h++){
            float e = lrelu(sv[h] + dsc[h]);
            if (e > m[h]){                      // warp-uniform branch
                float cr = __expf(m[h] - e);
                den[h] = den[h]*cr + 1.f;
                acc[h] = acc[h]*cr + yv;
                m[h] = e;
            } else {
                float p = __expf(e - m[h]);
                den[h] += p;
                acc[h] += p*yv;
            }
        }
    }
    float z[4];
    #pragma unroll
    for (int h = 0; h < 4; h++) z[h] = den[h] > 0.f ? acc[h]/den[h] : 0.f;
    // in-warp GEMM: lane holds z[h, f=lane]; output channel c = lane
    float o = 0.f;
    #pragma unroll
    for (int f = 0; f < HID; f++){
        float z0 = __shfl_sync(0xffffffffu, z[0], f);
        float z1 = __shfl_sync(0xffffffffu, z[1], f);
        float z2 = __shfl_sync(0xffffffffu, z[2], f);
        float z3 = __shfl_sync(0xffffffffu, z[3], f);
        const float* w = Ws + f*128;
        o += z0*w[lane] + z1*w[32+lane] + z2*w[64+lane] + z3*w[96+lane];
    }
    float contrib = o*0.25f + b2[t*HID + lane];  // head mean + bias
    atomicAdd(&g_out2[(c_dst[t]*NN + n)*HID + lane], contrib);
}

// ---------------- final: hetero mean + relu + channel concat ----------------
__global__ void final_kernel(float* __restrict__ out){
    int i = blockIdx.x*blockDim.x + threadIdx.x;
    if (i >= NN*NCH*HID) return;
    int n = i / (NCH*HID);
    int r = i % (NCH*HID);
    int c = r / HID, j = r % HID;
    float v = g_out2[(c*NN + n)*HID + j] * 0.25f;
    out[i] = v > 0.f ? v : 0.f;
}

extern "C" void kernel_launch(void* const* d_in, const int* in_sizes, int n_in,
                              void* d_out, int out_size){
    const float* x   = (const float*)d_in[0];
    const int*   edg = (const int*)  d_in[1];
    const float* W1  = (const float*)d_in[2];
    const float* as1 = (const float*)d_in[3];
    const float* ad1 = (const float*)d_in[4];
    const float* b1  = (const float*)d_in[5];
    const float* W2  = (const float*)d_in[6];
    const float* as2 = (const float*)d_in[7];
    const float* ad2 = (const float*)d_in[8];
    const float* b2  = (const float*)d_in[9];
    float* out = (float*)d_out;

    zero_kernel<<<2048, 256>>>();
    count_kernel<<<(NT*NE + 255)/256, 256>>>(edg);
    scan_kernel<<<NT, 1024>>>();
    fill_kernel<<<(NT*NE + 255)/256, 256>>>(edg);
    param_kernel<<<(NT*HID*4 + 255)/256, 256>>>(W1, as1, ad1, W2, as2, ad2);
    l1_edge_kernel<<<(NT*NN + 255)/256, 256>>>(x);
    l1_combine_kernel<<<(NCH*NN*HID + 255)/256, 256>>>(W1, b1);
    l2_score_kernel<<<(NT*NN + 255)/256, 256>>>();
    dim3 g2((NN + 7)/8, NT);
    l2_edge_kernel<<<g2, 256>>>(W2, b2);
    final_kernel<<<(NN*NCH*HID + 255)/256, 256>>>(out);
}

// round 3
// speedup vs baseline: 1.2154x; 1.2154x over previous
#include <cuda_runtime.h>
#include <math.h>

#define NCH 4
#define NN 20000
#define NE 320000
#define NT 16
#define HID 32
#define CHUNK 2048
#define NCHK 10   // ceil(20000/2048)

// edge-type metadata: 4 spatial (c->c) then 12 inter-channel (s!=d)
__constant__ int c_src[16] = {0,1,2,3, 0,0,0, 1,1,1, 2,2,2, 3,3,3};
__constant__ int c_dst[16] = {0,1,2,3, 1,2,3, 0,2,3, 0,1,3, 0,1,2};
__constant__ int c_in[4][4] = {{0,7,10,13},{1,4,11,14},{2,5,8,15},{3,6,9,12}};

// scratch (static device globals; no allocation)
__device__ int    g_count[NT*NN];
__device__ int    g_off[NT*(NN+1)];
__device__ int    g_cur[NT*NN];
__device__ int    g_col[NT*NE];
__device__ int    g_bsum[NT*NCHK];
__device__ int    g_bbase[NT*NCHK];
__device__ float4 g_za[NT*NN];          // layer1 per-(type,dst) head aggregates
__device__ float  g_y[NCH*NN*HID];      // layer1 output (post relu)
__device__ float4 g_s2[NT*NN];          // layer2 src scores per head
__device__ float4 g_d2[NT*NN];          // layer2 dst scores per head
__device__ float4 g_w[NT*NE];           // layer2 per-edge softmax weights (x0.25 folded)
__device__ float4 g_As2[NT*HID];        // W2^T @ att_src2 folded: [t][f][h]
__device__ float4 g_Ad2[NT*HID];
__device__ float4 g_SA[NT];             // layer1 folded score weights [t][h]
__device__ float4 g_DA[NT];

__device__ __forceinline__ float lrelu(float v){ return v > 0.f ? v : 0.2f*v; }

// ---------------- zero counters ----------------
__global__ void zero_kernel(){
    int i = blockIdx.x*blockDim.x + threadIdx.x;
    if (i < NT*NN) g_count[i] = 0;
}

// ---------------- CSR build: count (x4 ILP, int4 loads) ----------------
__global__ void count_kernel(const int* __restrict__ edges){
    int i = blockIdx.x*blockDim.x + threadIdx.x;
    if (i >= NT*NE/4) return;
    int t = (i*4) / NE, e = (i*4) % NE;
    int4 d4 = *(const int4*)(edges + t*2*NE + NE + e);
    atomicAdd(&g_count[t*NN + d4.x], 1);
    atomicAdd(&g_count[t*NN + d4.y], 1);
    atomicAdd(&g_count[t*NN + d4.z], 1);
    atomicAdd(&g_count[t*NN + d4.w], 1);
}

// ---------------- scan phase A: per-chunk block sums ----------------
__global__ void scanA_kernel(){
    __shared__ int sd[256];
    int b = blockIdx.x;               // b = t*NCHK + chunk
    int t = b / NCHK, chunk = b % NCHK;
    int tid = threadIdx.x;
    int base = chunk*CHUNK + tid*8;
    int s = 0;
    #pragma unroll
    for (int e = 0; e < 8; e++){
        int gi = base + e;
        if (gi < NN) s += g_count[t*NN + gi];
    }
    sd[tid] = s;
    __syncthreads();
    #pragma unroll
    for (int ofs = 128; ofs > 0; ofs >>= 1){
        if (tid < ofs) sd[tid] += sd[tid+ofs];
        __syncthreads();
    }
    if (tid == 0) g_bsum[b] = sd[0];
}

// ---------------- scan phase B: tiny per-type chunk scan ----------------
__global__ void scanB_kernel(){
    int t = threadIdx.x;
    if (t >= NT) return;
    int run = 0;
    for (int k = 0; k < NCHK; k++){
        g_bbase[t*NCHK + k] = run;
        run += g_bsum[t*NCHK + k];
    }
    g_off[t*(NN+1)] = 0;
}

// ---------------- scan phase C: per-chunk exclusive scan + write ----------------
__global__ void scanC_kernel(){
    __shared__ int sd[256];
    int b = blockIdx.x;
    int t = b / NCHK, chunk = b % NCHK;
    int tid = threadIdx.x;
    int base = chunk*CHUNK + tid*8;
    int c[8];
    int tsum = 0;
    #pragma unroll
    for (int e = 0; e < 8; e++){
        int gi = base + e;
        c[e] = (gi < NN) ? g_count[t*NN + gi] : 0;
        tsum += c[e];
    }
    sd[tid] = tsum;
    __syncthreads();
    #pragma unroll
    for (int ofs = 1; ofs < 256; ofs <<= 1){
        int add = (tid >= ofs) ? sd[tid-ofs] : 0;
        __syncthreads();
        sd[tid] += add;
        __syncthreads();
    }
    int run = sd[tid] - tsum + g_bbase[b];
    #pragma unroll
    for (int e = 0; e < 8; e++){
        int gi = base + e;
        if (gi < NN){
            g_cur[t*NN + gi] = run;
            run += c[e];
            g_off[t*(NN+1) + gi + 1] = run;
        }
    }
}

// ---------------- CSR build: fill (x4 ILP, int4 loads) ----------------
__global__ void fill_kernel(const int* __restrict__ edges){
    int i = blockIdx.x*blockDim.x + threadIdx.x;
    if (i >= NT*NE/4) return;
    int t = (i*4) / NE, e = (i*4) % NE;
    int4 s4 = *(const int4*)(edges + t*2*NE + e);
    int4 d4 = *(const int4*)(edges + t*2*NE + NE + e);
    int p0 = atomicAdd(&g_cur[t*NN + d4.x], 1);
    int p1 = atomicAdd(&g_cur[t*NN + d4.y], 1);
    int p2 = atomicAdd(&g_cur[t*NN + d4.z], 1);
    int p3 = atomicAdd(&g_cur[t*NN + d4.w], 1);
    g_col[t*NE + p0] = s4.x;
    g_col[t*NE + p1] = s4.y;
    g_col[t*NE + p2] = s4.z;
    g_col[t*NE + p3] = s4.w;
}

// ---------------- fold attention weights ----------------
__global__ void param_kernel(const float* __restrict__ W1, const float* __restrict__ as1,
                             const float* __restrict__ ad1,
                             const float* __restrict__ W2, const float* __restrict__ as2,
                             const float* __restrict__ ad2){
    int i = blockIdx.x*blockDim.x + threadIdx.x;
    if (i >= NT*HID*4) return;
    int t = i / (HID*4);
    int r = i % (HID*4);
    int f = r / 4, h = r % 4;
    float sa = 0.f, sd = 0.f;
    const float* wrow = W2 + (t*HID + f)*128 + h*32;
    const float* arow = as2 + (t*4 + h)*32;
    const float* drow = ad2 + (t*4 + h)*32;
    #pragma unroll
    for (int c = 0; c < 32; c++){ sa += wrow[c]*arow[c]; sd += wrow[c]*drow[c]; }
    ((float*)g_As2)[(t*HID + f)*4 + h] = sa;
    ((float*)g_Ad2)[(t*HID + f)*4 + h] = sd;
    if (f == 0){
        float s1 = 0.f, d1 = 0.f;
        const float* w1 = W1 + t*128 + h*32;
        const float* a1 = as1 + (t*4 + h)*32;
        const float* dd1 = ad1 + (t*4 + h)*32;
        #pragma unroll
        for (int c = 0; c < 32; c++){ s1 += w1[c]*a1[c]; d1 += w1[c]*dd1[c]; }
        ((float*)g_SA)[t*4 + h] = s1;
        ((float*)g_DA)[t*4 + h] = d1;
    }
}

// ---------------- layer-1 edge aggregation: thread per (type,dst) ----------------
// no max-subtraction: |scores| <= ~2 here, exp is safe and math is identical.
__global__ void l1_edge_kernel(const float* __restrict__ x){
    int i = blockIdx.x*blockDim.x + threadIdx.x;
    if (i >= NT*NN) return;
    int t = i / NN, n = i % NN;
    float4 SAv = g_SA[t];
    float4 DAv = g_DA[t];
    float SA[4] = {SAv.x, SAv.y, SAv.z, SAv.w};
    float DA[4] = {DAv.x, DAv.y, DAv.z, DAv.w};
    float xd = x[c_dst[t]*NN + n];
    float dsc[4];
    #pragma unroll
    for (int h = 0; h < 4; h++) dsc[h] = xd * DA[h];
    const float* xs = x + c_src[t]*NN;
    const int* col = g_col + t*NE;
    int beg = g_off[t*(NN+1) + n];
    int end = g_off[t*(NN+1) + n + 1];
    float den[4] = {0,0,0,0}, acc[4] = {0,0,0,0};
    for (int j = beg; j < end; j++){
        int s = col[j];
        float xv = xs[s];
        #pragma unroll
        for (int h = 0; h < 4; h++){
            float p = __expf(lrelu(xv*SA[h] + dsc[h]));
            den[h] += p;
            acc[h] += p*xv;
        }
    }
    float4 z;
    z.x = den[0] > 0.f ? acc[0]/den[0] : 0.f;
    z.y = den[1] > 0.f ? acc[1]/den[1] : 0.f;
    z.z = den[2] > 0.f ? acc[2]/den[2] : 0.f;
    z.w = den[3] > 0.f ? acc[3]/den[3] : 0.f;
    g_za[t*NN + n] = z;
}

// ---------------- layer-1 combine: rank-1 expansion + hetero mean + relu ----------------
__global__ void l1_combine_kernel(const float* __restrict__ W1, const float* __restrict__ b1){
    int i = blockIdx.x*blockDim.x + threadIdx.x;
    if (i >= NCH*NN*HID) return;
    int c = i / (NN*HID);
    int r = i % (NN*HID);
    int n = r / HID, j = r % HID;
    float v = 0.f;
    #pragma unroll
    for (int k = 0; k < 4; k++){
        int t = c_in[c][k];
        float4 za = g_za[t*NN + n];
        const float* w = W1 + t*128;
        float o = za.x*w[j] + za.y*w[32+j] + za.z*w[64+j] + za.w*w[96+j];
        v += o*0.25f + b1[t*HID + j];
    }
    v *= 0.25f;                       // hetero mean over 4 incoming types
    g_y[c*NN*HID + n*HID + j] = v > 0.f ? v : 0.f;
}

// ---------------- layer-2 score tables ----------------
__global__ void l2_score_kernel(){
    int i = blockIdx.x*blockDim.x + threadIdx.x;
    if (i >= NT*NN) return;
    int t = i / NN, n = i % NN;
    const float* ys = g_y + c_src[t]*NN*HID + n*HID;
    const float* yd = g_y + c_dst[t]*NN*HID + n*HID;
    float s[4] = {0,0,0,0}, d[4] = {0,0,0,0};
    #pragma unroll
    for (int f = 0; f < HID; f++){
        float4 a = g_As2[t*HID + f];
        float4 b = g_Ad2[t*HID + f];
        float yv = ys[f], ydv = yd[f];
        s[0] += yv*a.x; s[1] += yv*a.y; s[2] += yv*a.z; s[3] += yv*a.w;
        d[0] += ydv*b.x; d[1] += ydv*b.y; d[2] += ydv*b.z; d[3] += ydv*b.w;
    }
    g_s2[t*NN + n] = make_float4(s[0], s[1], s[2], s[3]);
    g_d2[t*NN + n] = make_float4(d[0], d[1], d[2], d[3]);
}

// ---------------- layer-2: thread per (type,dst) computes per-edge weights ----------------
// pass1: den per head (exp batched 32-edges per warp instruction);
// pass2: recompute p, store w = 0.25*p/den (head-mean folded in).
__global__ void l2_denw_kernel(){
    int i = blockIdx.x*blockDim.x + threadIdx.x;
    if (i >= NT*NN) return;
    int t = i / NN, n = i % NN;
    float4 d2v = g_d2[t*NN + n];
    float dsc[4] = {d2v.x, d2v.y, d2v.z, d2v.w};
    const float4* s2 = g_s2 + t*NN;
    const int* col = g_col + t*NE;
    int beg = g_off[t*(NN+1) + n];
    int end = g_off[t*(NN+1) + n + 1];
    float den[4] = {0,0,0,0};
    for (int j = beg; j < end; j++){
        float4 sv = s2[col[j]];
        den[0] += __expf(lrelu(sv.x + dsc[0]));
        den[1] += __expf(lrelu(sv.y + dsc[1]));
        den[2] += __expf(lrelu(sv.z + dsc[2]));
        den[3] += __expf(lrelu(sv.w + dsc[3]));
    }
    float rcp[4];
    #pragma unroll
    for (int h = 0; h < 4; h++) rcp[h] = den[h] > 0.f ? 0.25f/den[h] : 0.f;
    for (int j = beg; j < end; j++){
        float4 sv = s2[col[j]];
        float4 w;
        w.x = __expf(lrelu(sv.x + dsc[0]))*rcp[0];
        w.y = __expf(lrelu(sv.y + dsc[1]))*rcp[1];
        w.z = __expf(lrelu(sv.z + dsc[2]))*rcp[2];
        w.w = __expf(lrelu(sv.w + dsc[3]))*rcp[3];
        g_w[t*NE + j] = w;
    }
}

// ---------------- layer-2 gather + GEMM epilogue ----------------
// block = (32 dst nodes, one channel); warp per node loops the channel's 4
// incoming types. No exp, no div, no atomics: weights precomputed, output
// written directly with hetero-mean + relu. W2 held transposed in smem so
// the epilogue is LDS.128 z + LDS.128 Wt + 4 FFMA per f.
__global__ void __launch_bounds__(1024) l2_gather_kernel(const float* __restrict__ W2,
                                                         const float* __restrict__ b2,
                                                         float* __restrict__ out){
    extern __shared__ float4 smem4[];
    float4* Wt  = smem4;          // [4][32*32]: Wt[k][f*32+j] = {W2[f][h*32+j]}_h
    float4* zsm = smem4 + 4096;   // [32 warps][32]
    int c = blockIdx.y;
    for (int idx = threadIdx.x; idx < 4096; idx += 1024){
        int k = idx >> 10, r = idx & 1023;
        int f = r >> 5, j = r & 31;
        int t = c_in[c][k];
        const float* wb = W2 + (t*HID + f)*128 + j;
        Wt[idx] = make_float4(wb[0], wb[32], wb[64], wb[96]);
    }
    __syncthreads();
    int warp = threadIdx.x >> 5, lane = threadIdx.x & 31;
    int n = blockIdx.x*32 + warp;   // grid.x = 625, exact cover of 20000
    float o = 0.f, bsum = 0.f;
    #pragma unroll
    for (int k = 0; k < 4; k++){
        int t = c_in[c][k];
        const float* ysrc = g_y + c_src[t]*NN*HID;
        const int* col = g_col + t*NE;
        const float4* wrr = g_w + t*NE;
        int beg = g_off[t*(NN+1) + n];
        int end = g_off[t*(NN+1) + n + 1];
        float a0 = 0.f, a1 = 0.f, a2 = 0.f, a3 = 0.f;
        for (int j = beg; j < end; j++){
            int s = col[j];                   // warp-uniform
            float4 w = wrr[j];                // warp-uniform broadcast
            float yv = ysrc[s*HID + lane];    // coalesced 128B row
            a0 += w.x*yv; a1 += w.y*yv; a2 += w.z*yv; a3 += w.w*yv;
        }
        zsm[warp*32 + lane] = make_float4(a0, a1, a2, a3);
        __syncwarp();
        const float4* wt = Wt + k*1024;
        #pragma unroll
        for (int f = 0; f < 32; f++){
            float4 z = zsm[warp*32 + f];
            float4 wv = wt[f*32 + lane];
            o += z.x*wv.x + z.y*wv.y + z.z*wv.z + z.w*wv.w;
        }
        bsum += b2[t*HID + lane];
        __syncwarp();
    }
    float v = (o + bsum)*0.25f;               // hetero mean over 4 types
    out[n*(NCH*HID) + c*HID + lane] = v > 0.f ? v : 0.f;
}

extern "C" void kernel_launch(void* const* d_in, const int* in_sizes, int n_in,
                              void* d_out, int out_size){
    const float* x   = (const float*)d_in[0];
    const int*   edg = (const int*)  d_in[1];
    const float* W1  = (const float*)d_in[2];
    const float* as1 = (const float*)d_in[3];
    const float* ad1 = (const float*)d_in[4];
    const float* b1  = (const float*)d_in[5];
    const float* W2  = (const float*)d_in[6];
    const float* as2 = (const float*)d_in[7];
    const float* ad2 = (const float*)d_in[8];
    const float* b2  = (const float*)d_in[9];
    float* out = (float*)d_out;

    static bool attr_set = false;
    if (!attr_set){
        cudaFuncSetAttribute(l2_gather_kernel,
                             cudaFuncAttributeMaxDynamicSharedMemorySize, 82*1024);
        attr_set = true;
    }

    zero_kernel<<<(NT*NN + 255)/256, 256>>>();
    count_kernel<<<(NT*NE/4 + 255)/256, 256>>>(edg);
    scanA_kernel<<<NT*NCHK, 256>>>();
    scanB_kernel<<<1, 32>>>();
    scanC_kernel<<<NT*NCHK, 256>>>();
    fill_kernel<<<(NT*NE/4 + 255)/256, 256>>>(edg);
    param_kernel<<<(NT*HID*4 + 255)/256, 256>>>(W1, as1, ad1, W2, as2, ad2);
    l1_edge_kernel<<<(NT*NN + 255)/256, 256>>>(x);
    l1_combine_kernel<<<(NCH*NN*HID + 255)/256, 256>>>(W1, b1);
    l2_score_kernel<<<(NT*NN + 255)/256, 256>>>();
    l2_denw_kernel<<<(NT*NN + 255)/256, 256>>>();
    dim3 g2(NN/32, NCH);   // 625 x 4
    l2_gather_kernel<<<g2, 1024, 82*1024>>>(W2, b2, out);
}

// round 8
// speedup vs baseline: 1.6692x; 1.3734x over previous
#include <cuda_runtime.h>
#include <math.h>

#define NCH 4
#define NN 20000
#define NE 320000
#define NT 16
#define HID 32
#define CHUNK 2048
#define NCHK 10   // ceil(20000/2048)
#define CAP 64    // per-warp p-tile capacity in l2_gather

// edge-type metadata: 4 spatial (c->c) then 12 inter-channel (s!=d)
__constant__ int c_src[16] = {0,1,2,3, 0,0,0, 1,1,1, 2,2,2, 3,3,3};
__constant__ int c_dst[16] = {0,1,2,3, 1,2,3, 0,2,3, 0,1,3, 0,1,2};
__constant__ int c_in[4][4] = {{0,7,10,13},{1,4,11,14},{2,5,8,15},{3,6,9,12}};

// scratch (static device globals; no allocation)
__device__ int    g_cur[NT*NN];
__device__ int    g_off[NT*(NN+1)];
__device__ int    g_rank[NT*NE];
__device__ int    g_col[NT*NE];
__device__ int    g_bsum[NT*NCHK];
__device__ int    g_bbase[NT*NCHK];
__device__ float4 g_za[NT*NN];          // layer1 per-(type,dst) head aggregates
__device__ float  g_y[NCH*NN*HID];      // layer1 output (post relu)
__device__ float4 g_s2[NT*NN];          // layer2 src scores per head
__device__ float4 g_d2[NT*NN];          // layer2 dst scores per head
__device__ float4 g_As2[NT*HID];        // W2^T @ att_src2 folded: [t][f][h]
__device__ float4 g_Ad2[NT*HID];
__device__ float4 g_SA[NT];             // layer1 folded score weights [t][h]
__device__ float4 g_DA[NT];
__device__ float4 g_Wt[NT*HID*HID];     // W2 transposed: [t][f][j] = {W2[t][f][h*32+j]}_h

__device__ __forceinline__ float lrelu(float v){ return v > 0.f ? v : 0.2f*v; }

// ---- packed f32x2 helpers (sm_103a) ----
__device__ __forceinline__ unsigned long long pk2(float lo, float hi){
    unsigned long long r;
    asm("mov.b64 %0, {%1, %2};" : "=l"(r) : "f"(lo), "f"(hi));
    return r;
}
__device__ __forceinline__ void fma2(unsigned long long& d, unsigned long long a,
                                     unsigned long long b){
    asm("fma.rn.f32x2 %0, %1, %2, %3;" : "=l"(d) : "l"(a), "l"(b), "l"(d));
}
__device__ __forceinline__ void mul2(unsigned long long& d, unsigned long long a,
                                     unsigned long long b){
    asm("mul.rn.f32x2 %0, %1, %2;" : "=l"(d) : "l"(a), "l"(b));
}
__device__ __forceinline__ float2 upk2(unsigned long long v){
    float2 r;
    asm("mov.b64 {%0, %1}, %2;" : "=f"(r.x), "=f"(r.y) : "l"(v));
    return r;
}

// ---------------- zero cursors ----------------
__global__ void zero_kernel(){
    int i = blockIdx.x*blockDim.x + threadIdx.x;
    if (i < NT*NN) g_cur[i] = 0;
}

// ---------------- CSR: rank pass (one atomic pass; stores per-edge rank) ----------------
__global__ void rank_kernel(const int* __restrict__ edges){
    int i = blockIdx.x*blockDim.x + threadIdx.x;
    if (i >= NT*NE/4) return;
    int t = (i*4) / NE, e = (i*4) % NE;
    int4 d4 = *(const int4*)(edges + t*2*NE + NE + e);
    int r0 = atomicAdd(&g_cur[t*NN + d4.x], 1);
    int r1 = atomicAdd(&g_cur[t*NN + d4.y], 1);
    int r2 = atomicAdd(&g_cur[t*NN + d4.z], 1);
    int r3 = atomicAdd(&g_cur[t*NN + d4.w], 1);
    *(int4*)(g_rank + t*NE + e) = make_int4(r0, r1, r2, r3);
}

// ---------------- scan A: per-chunk sums of counts (in g_cur) ----------------
__global__ void scanA_kernel(){
    __shared__ int sd[256];
    int b = blockIdx.x;               // b = t*NCHK + chunk
    int t = b / NCHK, chunk = b % NCHK;
    int tid = threadIdx.x;
    int base = chunk*CHUNK + tid*8;
    int s = 0;
    #pragma unroll
    for (int e = 0; e < 8; e++){
        int gi = base + e;
        if (gi < NN) s += g_cur[t*NN + gi];
    }
    sd[tid] = s;
    __syncthreads();
    #pragma unroll
    for (int ofs = 128; ofs > 0; ofs >>= 1){
        if (tid < ofs) sd[tid] += sd[tid+ofs];
        __syncthreads();
    }
    if (tid == 0) g_bsum[b] = sd[0];
}

// ---------------- scan B: tiny per-type chunk scan ----------------
__global__ void scanB_kernel(){
    int t = threadIdx.x;
    if (t >= NT) return;
    int run = 0;
    for (int k = 0; k < NCHK; k++){
        g_bbase[t*NCHK + k] = run;
        run += g_bsum[t*NCHK + k];
    }
    g_off[t*(NN+1)] = 0;
}

// ---------------- scan C: per-chunk exclusive scan -> g_off ----------------
__global__ void scanC_kernel(){
    __shared__ int sd[256];
    int b = blockIdx.x;
    int t = b / NCHK, chunk = b % NCHK;
    int tid = threadIdx.x;
    int base = chunk*CHUNK + tid*8;
    int c[8];
    int tsum = 0;
    #pragma unroll
    for (int e = 0; e < 8; e++){
        int gi = base + e;
        c[e] = (gi < NN) ? g_cur[t*NN + gi] : 0;
        tsum += c[e];
    }
    sd[tid] = tsum;
    __syncthreads();
    #pragma unroll
    for (int ofs = 1; ofs < 256; ofs <<= 1){
        int add = (tid >= ofs) ? sd[tid-ofs] : 0;
        __syncthreads();
        sd[tid] += add;
        __syncthreads();
    }
    int run = sd[tid] - tsum + g_bbase[b];
    #pragma unroll
    for (int e = 0; e < 8; e++){
        int gi = base + e;
        if (gi < NN){
            run += c[e];
            g_off[t*(NN+1) + gi + 1] = run;
        }
    }
}

// ---------------- CSR: scatter (no atomics) ----------------
__global__ void scatter_kernel(const int* __restrict__ edges){
    int i = blockIdx.x*blockDim.x + threadIdx.x;
    if (i >= NT*NE/4) return;
    int t = (i*4) / NE, e = (i*4) % NE;
    int4 s4 = *(const int4*)(edges + t*2*NE + e);
    int4 d4 = *(const int4*)(edges + t*2*NE + NE + e);
    int4 r4 = *(const int4*)(g_rank + t*NE + e);
    const int* offT = g_off + t*(NN+1);
    int* colT = g_col + t*NE;
    colT[offT[d4.x] + r4.x] = s4.x;
    colT[offT[d4.y] + r4.y] = s4.y;
    colT[offT[d4.z] + r4.z] = s4.z;
    colT[offT[d4.w] + r4.w] = s4.w;
}

// ---------------- fold attention weights ----------------
__global__ void param_kernel(const float* __restrict__ W1, const float* __restrict__ as1,
                             const float* __restrict__ ad1,
                             const float* __restrict__ W2, const float* __restrict__ as2,
                             const float* __restrict__ ad2){
    int i = blockIdx.x*blockDim.x + threadIdx.x;
    if (i >= NT*HID*4) return;
    int t = i / (HID*4);
    int r = i % (HID*4);
    int f = r / 4, h = r % 4;
    float sa = 0.f, sd = 0.f;
    const float* wrow = W2 + (t*HID + f)*128 + h*32;
    const float* arow = as2 + (t*4 + h)*32;
    const float* drow = ad2 + (t*4 + h)*32;
    #pragma unroll
    for (int c = 0; c < 32; c++){ sa += wrow[c]*arow[c]; sd += wrow[c]*drow[c]; }
    ((float*)g_As2)[(t*HID + f)*4 + h] = sa;
    ((float*)g_Ad2)[(t*HID + f)*4 + h] = sd;
    if (f == 0){
        float s1 = 0.f, d1 = 0.f;
        const float* w1 = W1 + t*128 + h*32;
        const float* a1 = as1 + (t*4 + h)*32;
        const float* dd1 = ad1 + (t*4 + h)*32;
        #pragma unroll
        for (int c = 0; c < 32; c++){ s1 += w1[c]*a1[c]; d1 += w1[c]*dd1[c]; }
        ((float*)g_SA)[t*4 + h] = s1;
        ((float*)g_DA)[t*4 + h] = d1;
    }
}

// ---------------- transpose W2 -> g_Wt once ----------------
__global__ void wt_kernel(const float* __restrict__ W2){
    int i = blockIdx.x*blockDim.x + threadIdx.x;
    if (i >= NT*HID*HID) return;
    int t = i / 1024;
    int r = i % 1024;
    int f = r / 32, j = r % 32;
    const float* wb = W2 + (t*HID + f)*128 + j;
    g_Wt[i] = make_float4(wb[0], wb[32], wb[64], wb[96]);
}

// ---------------- layer-1 edge aggregation: thread per (type,dst) ----------------
__global__ void l1_edge_kernel(const float* __restrict__ x){
    int i = blockIdx.x*blockDim.x + threadIdx.x;
    if (i >= NT*NN) return;
    int t = i / NN, n = i % NN;
    float4 SAv = g_SA[t];
    float4 DAv = g_DA[t];
    float SA[4] = {SAv.x, SAv.y, SAv.z, SAv.w};
    float DA[4] = {DAv.x, DAv.y, DAv.z, DAv.w};
    float xd = x[c_dst[t]*NN + n];
    float dsc[4];
    #pragma unroll
    for (int h = 0; h < 4; h++) dsc[h] = xd * DA[h];
    const float* xs = x + c_src[t]*NN;
    const int* col = g_col + t*NE;
    int beg = g_off[t*(NN+1) + n];
    int end = g_off[t*(NN+1) + n + 1];
    float den[4] = {0,0,0,0}, acc[4] = {0,0,0,0};
    for (int j = beg; j < end; j++){
        int s = col[j];
        float xv = xs[s];
        #pragma unroll
        for (int h = 0; h < 4; h++){
            float p = __expf(lrelu(xv*SA[h] + dsc[h]));
            den[h] += p;
            acc[h] += p*xv;
        }
    }
    float4 z;
    z.x = den[0] > 0.f ? acc[0]/den[0] : 0.f;
    z.y = den[1] > 0.f ? acc[1]/den[1] : 0.f;
    z.z = den[2] > 0.f ? acc[2]/den[2] : 0.f;
    z.w = den[3] > 0.f ? acc[3]/den[3] : 0.f;
    g_za[t*NN + n] = z;
}

// ---------------- layer-1 combine: rank-1 expansion + hetero mean + relu ----------------
__global__ void l1_combine_kernel(const float* __restrict__ W1, const float* __restrict__ b1){
    int i = blockIdx.x*blockDim.x + threadIdx.x;
    if (i >= NCH*NN*HID) return;
    int c = i / (NN*HID);
    int r = i % (NN*HID);
    int n = r / HID, j = r % HID;
    float v = 0.f;
    #pragma unroll
    for (int k = 0; k < 4; k++){
        int t = c_in[c][k];
        float4 za = g_za[t*NN + n];
        const float* w = W1 + t*128;
        float o = za.x*w[j] + za.y*w[32+j] + za.z*w[64+j] + za.w*w[96+j];
        v += o*0.25f + b1[t*HID + j];
    }
    v *= 0.25f;                       // hetero mean over 4 incoming types
    g_y[c*NN*HID + n*HID + j] = v > 0.f ? v : 0.f;
}

// ---------------- layer-2 score tables ----------------
__global__ void l2_score_kernel(){
    int i = blockIdx.x*blockDim.x + threadIdx.x;
    if (i >= NT*NN) return;
    int t = i / NN, n = i % NN;
    const float* ys = g_y + c_src[t]*NN*HID + n*HID;
    const float* yd = g_y + c_dst[t]*NN*HID + n*HID;
    float s[4] = {0,0,0,0}, d[4] = {0,0,0,0};
    #pragma unroll
    for (int f = 0; f < HID; f++){
        float4 a = g_As2[t*HID + f];
        float4 b = g_Ad2[t*HID + f];
        float yv = ys[f], ydv = yd[f];
        s[0] += yv*a.x; s[1] += yv*a.y; s[2] += yv*a.z; s[3] += yv*a.w;
        d[0] += ydv*b.x; d[1] += ydv*b.y; d[2] += ydv*b.z; d[3] += ydv*b.w;
    }
    g_s2[t*NN + n] = make_float4(s[0], s[1], s[2], s[3]);
    g_d2[t*NN + n] = make_float4(d[0], d[1], d[2], d[3]);
}

// ---------------- layer-2 fused: softmax + gather + block-GEMM epilogue ----------------
// Phase 1 (warp per dst node, 4 types): lane-parallel exp into per-warp smem
// p-tiles (single exp pass for deg<=CAP), warp-reduce den, serial y-row gather
// with packed f32x2 FMAs, normalize once, stage z into zsm[k][n][f].
// Phase 2 (block GEMM): Out[32n][32j] = sum_k Z_k * Wt_k with 2x2 register
// tiles + k split over 4 thread groups -> 4x less smem crossbar traffic.
__global__ void __launch_bounds__(1024) l2_gather_kernel(const float* __restrict__ b2,
                                                         float* __restrict__ out){
    extern __shared__ float smemf[];
    float4* Wt  = (float4*)smemf;                 // [4][32f][32j] f4(h): 64 KB
    float4* zsm = (float4*)(smemf + 16384);       // [4][32n][32f] f4(h): 64 KB
    float4* wbA = (float4*)(smemf + 32768);       // [32 warps][CAP]:     32 KB
    int*    cbA = (int*)  (smemf + 40960);        // [32 warps][CAP]:      8 KB
    float*  psum = (float*)wbA;                   // reused in phase 2:   16 KB
    int c = blockIdx.y;
    int tid = threadIdx.x;
    for (int idx = tid; idx < 4096; idx += 1024){
        int k = idx >> 10;
        Wt[idx] = g_Wt[c_in[c][k]*1024 + (idx & 1023)];
    }
    int warp = tid >> 5, lane = tid & 31;
    int n = blockIdx.x*32 + warp;                 // grid.x = 625, exact cover
    float4* wb = wbA + warp*CAP;
    int* cb = cbA + warp*CAP;
    #pragma unroll
    for (int k = 0; k < 4; k++){
        int t = c_in[c][k];
        const float* ysrc = g_y + c_src[t]*NN*HID;
        const int* col = g_col + t*NE;
        const float4* s2 = g_s2 + t*NN;
        int beg = g_off[t*(NN+1) + n], end = g_off[t*(NN+1) + n + 1];
        int deg = end - beg;
        float4 dv = g_d2[t*NN + n];
        float d0 = 0.f, d1 = 0.f, d2 = 0.f, d3 = 0.f;
        unsigned long long a01 = 0ull, a23 = 0ull;
        if (deg <= CAP){
            for (int base = 0; base < deg; base += 32){
                int j = base + lane;
                if (j < deg){
                    int s = col[beg + j];
                    float4 sv = s2[s];
                    float4 p;
                    p.x = __expf(lrelu(sv.x + dv.x));
                    p.y = __expf(lrelu(sv.y + dv.y));
                    p.z = __expf(lrelu(sv.z + dv.z));
                    p.w = __expf(lrelu(sv.w + dv.w));
                    d0 += p.x; d1 += p.y; d2 += p.z; d3 += p.w;
                    wb[j] = p; cb[j] = s;
                }
            }
            __syncwarp();
            #pragma unroll
            for (int o = 16; o; o >>= 1){
                d0 += __shfl_xor_sync(0xffffffffu, d0, o);
                d1 += __shfl_xor_sync(0xffffffffu, d1, o);
                d2 += __shfl_xor_sync(0xffffffffu, d2, o);
                d3 += __shfl_xor_sync(0xffffffffu, d3, o);
            }
            int i = 0;
            for (; i + 1 < deg; i += 2){        // ILP2 on the y-row gather
                ulonglong2 pw0 = *(const ulonglong2*)(wb + i);
                ulonglong2 pw1 = *(const ulonglong2*)(wb + i + 1);
                int s0 = cb[i], s1 = cb[i+1];
                float y0 = ysrc[s0*HID + lane];
                float y1 = ysrc[s1*HID + lane];
                unsigned long long y20 = pk2(y0, y0);
                unsigned long long y21 = pk2(y1, y1);
                fma2(a01, pw0.x, y20); fma2(a23, pw0.y, y20);
                fma2(a01, pw1.x, y21); fma2(a23, pw1.y, y21);
            }
            if (i < deg){
                ulonglong2 pw = *(const ulonglong2*)(wb + i);
                float yv = ysrc[cb[i]*HID + lane];
                unsigned long long y2 = pk2(yv, yv);
                fma2(a01, pw.x, y2); fma2(a23, pw.y, y2);
            }
            __syncwarp();
        } else {                                  // rare fallback: recompute path
            for (int base = beg; base < end; base += 32){
                int j = base + lane;
                if (j < end){
                    int s = col[j];
                    float4 sv = s2[s];
                    d0 += __expf(lrelu(sv.x + dv.x));
                    d1 += __expf(lrelu(sv.y + dv.y));
                    d2 += __expf(lrelu(sv.z + dv.z));
                    d3 += __expf(lrelu(sv.w + dv.w));
                }
            }
            #pragma unroll
            for (int o = 16; o; o >>= 1){
                d0 += __shfl_xor_sync(0xffffffffu, d0, o);
                d1 += __shfl_xor_sync(0xffffffffu, d1, o);
                d2 += __shfl_xor_sync(0xffffffffu, d2, o);
                d3 += __shfl_xor_sync(0xffffffffu, d3, o);
            }
            for (int base = beg; base < end; base += 32){
                int j = base + lane;
                int m = min(32, end - base);
                if (j < end){
                    int s = col[j];
                    float4 sv = s2[s];
                    float4 p;
                    p.x = __expf(lrelu(sv.x + dv.x));
                    p.y = __expf(lrelu(sv.y + dv.y));
                    p.z = __expf(lrelu(sv.z + dv.z));
                    p.w = __expf(lrelu(sv.w + dv.w));
                    wb[lane] = p; cb[lane] = s;
                }
                __syncwarp();
                for (int i = 0; i < m; i++){
                    ulonglong2 pw = *(const ulonglong2*)(wb + i);
                    float yv = ysrc[cb[i]*HID + lane];
                    unsigned long long y2 = pk2(yv, yv);
                    fma2(a01, pw.x, y2); fma2(a23, pw.y, y2);
                }
                __syncwarp();
            }
        }
        unsigned long long r01 = pk2(d0 > 0.f ? __fdividef(0.25f, d0) : 0.f,
                                     d1 > 0.f ? __fdividef(0.25f, d1) : 0.f);
        unsigned long long r23 = pk2(d2 > 0.f ? __fdividef(0.25f, d2) : 0.f,
                                     d3 > 0.f ? __fdividef(0.25f, d3) : 0.f);
        mul2(a01, a01, r01);
        mul2(a23, a23, r23);
        *(ulonglong2*)(zsm + (k*32 + warp)*32 + lane) = make_ulonglong2(a01, a23);
    }
    __syncthreads();
    // phase 2: block GEMM, 2x2 tiles, k split over thread groups
    {
        int g  = tid >> 8;            // k
        int r  = tid & 255;
        int tn = r >> 4;              // 0..15
        int tj = r & 15;              // 0..15
        const float4* Zk = zsm + g*1024;
        const float4* Wk = Wt  + g*1024;
        unsigned long long aA00=0ull, aB00=0ull, aA01=0ull, aB01=0ull;
        unsigned long long aA10=0ull, aB10=0ull, aA11=0ull, aB11=0ull;
        #pragma unroll 4
        for (int f = 0; f < 32; f++){
            ulonglong2 z0 = *(const ulonglong2*)(Zk + tn*32 + f);
            ulonglong2 z1 = *(const ulonglong2*)(Zk + (tn+16)*32 + f);
            ulonglong2 w0 = *(const ulonglong2*)(Wk + f*32 + tj);
            ulonglong2 w1 = *(const ulonglong2*)(Wk + f*32 + tj + 16);
            fma2(aA00, z0.x, w0.x); fma2(aB00, z0.y, w0.y);
            fma2(aA01, z0.x, w1.x); fma2(aB01, z0.y, w1.y);
            fma2(aA10, z1.x, w0.x); fma2(aB10, z1.y, w0.y);
            fma2(aA11, z1.x, w1.x); fma2(aB11, z1.y, w1.y);
        }
        __syncthreads();              // all zsm reads done before psum (aliases wbA)
        float2 A, B;
        A = upk2(aA00); B = upk2(aB00);
        psum[(g*32 + tn   )*32 + tj   ] = A.x + A.y + B.x + B.y;
        A = upk2(aA01); B = upk2(aB01);
        psum[(g*32 + tn   )*32 + tj+16] = A.x + A.y + B.x + B.y;
        A = upk2(aA10); B = upk2(aB10);
        psum[(g*32 + tn+16)*32 + tj   ] = A.x + A.y + B.x + B.y;
        A = upk2(aA11); B = upk2(aB11);
        psum[(g*32 + tn+16)*32 + tj+16] = A.x + A.y + B.x + B.y;
    }
    __syncthreads();
    {
        int nn = tid >> 5, j = tid & 31;
        float o = psum[nn*32 + j] + psum[1024 + nn*32 + j]
                + psum[2048 + nn*32 + j] + psum[3072 + nn*32 + j];
        float bs = b2[c_in[c][0]*HID + j] + b2[c_in[c][1]*HID + j]
                 + b2[c_in[c][2]*HID + j] + b2[c_in[c][3]*HID + j];
        float v = (o + bs)*0.25f;     // hetero mean over 4 types
        int ng = blockIdx.x*32 + nn;
        out[ng*(NCH*HID) + c*HID + j] = v > 0.f ? v : 0.f;
    }
}

extern "C" void kernel_launch(void* const* d_in, const int* in_sizes, int n_in,
                              void* d_out, int out_size){
    const float* x   = (const float*)d_in[0];
    const int*   edg = (const int*)  d_in[1];
    const float* W1  = (const float*)d_in[2];
    const float* as1 = (const float*)d_in[3];
    const float* ad1 = (const float*)d_in[4];
    const float* b1  = (const float*)d_in[5];
    const float* W2  = (const float*)d_in[6];
    const float* as2 = (const float*)d_in[7];
    const float* ad2 = (const float*)d_in[8];
    const float* b2  = (const float*)d_in[9];
    float* out = (float*)d_out;

    static bool attr_set = false;
    if (!attr_set){
        cudaFuncSetAttribute(l2_gather_kernel,
                             cudaFuncAttributeMaxDynamicSharedMemorySize, 172032);
        attr_set = true;
    }

    zero_kernel<<<(NT*NN + 255)/256, 256>>>();
    rank_kernel<<<(NT*NE/4 + 255)/256, 256>>>(edg);
    scanA_kernel<<<NT*NCHK, 256>>>();
    scanB_kernel<<<1, 32>>>();
    scanC_kernel<<<NT*NCHK, 256>>>();
    scatter_kernel<<<(NT*NE/4 + 255)/256, 256>>>(edg);
    param_kernel<<<(NT*HID*4 + 255)/256, 256>>>(W1, as1, ad1, W2, as2, ad2);
    wt_kernel<<<(NT*HID*HID + 255)/256, 256>>>(W2);
    l1_edge_kernel<<<(NT*NN + 255)/256, 256>>>(x);
    l1_combine_kernel<<<(NCH*NN*HID + 255)/256, 256>>>(W1, b1);
    l2_score_kernel<<<(NT*NN + 255)/256, 256>>>();
    dim3 g2(NN/32, NCH);   // 625 x 4
    l2_gather_kernel<<<g2, 1024, 172032>>>(b2, out);
}

// round 9
// speedup vs baseline: 1.9257x; 1.1537x over previous
#include <cuda_runtime.h>
#include <math.h>

#define NCH 4
#define NN 20000
#define NE 320000
#define NT 16
#define HID 32
#define CHUNK 2048
#define NCHK 10    // ceil(20000/2048)
#define CAP 64     // per-warp p-tile capacity in l2_gather
#define NBLK 8     // histogram blocks per edge type
#define SL (NE/NBLK)

// edge-type metadata: 4 spatial (c->c) then 12 inter-channel (s!=d)
__constant__ int c_src[16] = {0,1,2,3, 0,0,0, 1,1,1, 2,2,2, 3,3,3};
__constant__ int c_dst[16] = {0,1,2,3, 1,2,3, 0,2,3, 0,1,3, 0,1,2};
__constant__ int c_in[4][4]  = {{0,7,10,13},{1,4,11,14},{2,5,8,15},{3,6,9,12}};  // dst==c
__constant__ int c_out[4][4] = {{0,4,5,6},{1,7,8,9},{2,10,11,12},{3,13,14,15}};  // src==c

// scratch (static device globals; no allocation)
__device__ int    g_pc[NT*NBLK*NN];     // per-(type,block) partial counts -> prefixes
__device__ int    g_cnt[NT*NN];         // per-(type,node) total counts
__device__ int    g_off[NT*(NN+1)];
__device__ int    g_col[NT*NE];
__device__ int    g_bsum[NT*NCHK];
__device__ int    g_bbase[NT*NCHK];
__device__ float4 g_za[NT*NN];          // layer1 per-(type,dst) head aggregates
__device__ float  g_y[NCH*NN*HID];      // layer1 output (post relu)
__device__ float4 g_s2[NT*NN];          // layer2 src scores per head
__device__ float4 g_d2[NT*NN];          // layer2 dst scores per head
__device__ float4 g_As2[NT*HID];        // W2^T @ att_src2 folded: [t][f][h]
__device__ float4 g_Ad2[NT*HID];
__device__ float4 g_SA[NT];             // layer1 folded score weights [t][h]
__device__ float4 g_DA[NT];
__device__ float4 g_Wt[NT*HID*HID];     // W2 transposed: [t][f][j] = {W2[t][f][h*32+j]}_h

__device__ __forceinline__ float lrelu(float v){ return v > 0.f ? v : 0.2f*v; }

// ---- packed f32x2 helpers (sm_103a) ----
__device__ __forceinline__ unsigned long long pk2(float lo, float hi){
    unsigned long long r;
    asm("mov.b64 %0, {%1, %2};" : "=l"(r) : "f"(lo), "f"(hi));
    return r;
}
__device__ __forceinline__ void fma2(unsigned long long& d, unsigned long long a,
                                     unsigned long long b){
    asm("fma.rn.f32x2 %0, %1, %2, %3;" : "=l"(d) : "l"(a), "l"(b), "l"(d));
}
__device__ __forceinline__ void mul2(unsigned long long& d, unsigned long long a,
                                     unsigned long long b){
    asm("mul.rn.f32x2 %0, %1, %2;" : "=l"(d) : "l"(a), "l"(b));
}
__device__ __forceinline__ float2 upk2(unsigned long long v){
    float2 r;
    asm("mov.b64 {%0, %1}, %2;" : "=f"(r.x), "=f"(r.y) : "l"(v));
    return r;
}

// ---------------- CSR: smem histogram count (no global atomics) ----------------
__global__ void __launch_bounds__(1024) count_kernel(const int* __restrict__ edges){
    extern __shared__ int hist[];           // [NN] = 80 KB
    int b = blockIdx.x;                     // b = t*NBLK + blk
    int t = b >> 3, blk = b & 7;
    for (int i = threadIdx.x; i < NN; i += 1024) hist[i] = 0;
    __syncthreads();
    const int4* dstp = (const int4*)(edges + t*2*NE + NE + blk*SL);
    for (int i = threadIdx.x; i < SL/4; i += 1024){
        int4 d4 = dstp[i];
        atomicAdd(&hist[d4.x], 1);
        atomicAdd(&hist[d4.y], 1);
        atomicAdd(&hist[d4.z], 1);
        atomicAdd(&hist[d4.w], 1);
    }
    __syncthreads();
    int* pc = g_pc + b*NN;
    for (int i = threadIdx.x; i < NN; i += 1024) pc[i] = hist[i];
}

// ---------------- CSR: per-node prefix over the NBLK partials ----------------
__global__ void pprefix_kernel(){
    int i = blockIdx.x*blockDim.x + threadIdx.x;
    if (i >= NT*NN) return;
    int t = i / NN, n = i - t*NN;
    int run = 0;
    #pragma unroll
    for (int b = 0; b < NBLK; b++){
        int idx = (t*NBLK + b)*NN + n;
        int v = g_pc[idx];
        g_pc[idx] = run;                    // exclusive prefix across blocks
        run += v;
    }
    g_cnt[t*NN + n] = run;
}

// ---------------- scan A: per-chunk sums of counts ----------------
__global__ void scanA_kernel(){
    __shared__ int sd[256];
    int b = blockIdx.x;               // b = t*NCHK + chunk
    int t = b / NCHK, chunk = b % NCHK;
    int tid = threadIdx.x;
    int base = chunk*CHUNK + tid*8;
    int s = 0;
    #pragma unroll
    for (int e = 0; e < 8; e++){
        int gi = base + e;
        if (gi < NN) s += g_cnt[t*NN + gi];
    }
    sd[tid] = s;
    __syncthreads();
    #pragma unroll
    for (int ofs = 128; ofs > 0; ofs >>= 1){
        if (tid < ofs) sd[tid] += sd[tid+ofs];
        __syncthreads();
    }
    if (tid == 0) g_bsum[b] = sd[0];
}

// ---------------- scan B: tiny per-type chunk scan ----------------
__global__ void scanB_kernel(){
    int t = threadIdx.x;
    if (t >= NT) return;
    int run = 0;
    for (int k = 0; k < NCHK; k++){
        g_bbase[t*NCHK + k] = run;
        run += g_bsum[t*NCHK + k];
    }
    g_off[t*(NN+1)] = 0;
}

// ---------------- scan C: per-chunk exclusive scan -> g_off ----------------
__global__ void scanC_kernel(){
    __shared__ int sd[256];
    int b = blockIdx.x;
    int t = b / NCHK, chunk = b % NCHK;
    int tid = threadIdx.x;
    int base = chunk*CHUNK + tid*8;
    int c[8];
    int tsum = 0;
    #pragma unroll
    for (int e = 0; e < 8; e++){
        int gi = base + e;
        c[e] = (gi < NN) ? g_cnt[t*NN + gi] : 0;
        tsum += c[e];
    }
    sd[tid] = tsum;
    __syncthreads();
    #pragma unroll
    for (int ofs = 1; ofs < 256; ofs <<= 1){
        int add = (tid >= ofs) ? sd[tid-ofs] : 0;
        __syncthreads();
        sd[tid] += add;
        __syncthreads();
    }
    int run = sd[tid] - tsum + g_bbase[b];
    #pragma unroll
    for (int e = 0; e < 8; e++){
        int gi = base + e;
        if (gi < NN){
            run += c[e];
            g_off[t*(NN+1) + gi + 1] = run;
        }
    }
}

// ---------------- CSR: fill via smem cursors (no global atomics) ----------------
__global__ void __launch_bounds__(1024) fill_kernel(const int* __restrict__ edges){
    extern __shared__ int cur[];            // [NN] = 80 KB
    int b = blockIdx.x;
    int t = b >> 3, blk = b & 7;
    const int* offT = g_off + t*(NN+1);
    const int* pc = g_pc + b*NN;
    for (int i = threadIdx.x; i < NN; i += 1024) cur[i] = offT[i] + pc[i];
    __syncthreads();
    const int4* srcp = (const int4*)(edges + t*2*NE + blk*SL);
    const int4* dstp = (const int4*)(edges + t*2*NE + NE + blk*SL);
    int* colT = g_col + t*NE;
    for (int i = threadIdx.x; i < SL/4; i += 1024){
        int4 s4 = srcp[i];
        int4 d4 = dstp[i];
        int p0 = atomicAdd(&cur[d4.x], 1);
        int p1 = atomicAdd(&cur[d4.y], 1);
        int p2 = atomicAdd(&cur[d4.z], 1);
        int p3 = atomicAdd(&cur[d4.w], 1);
        colT[p0] = s4.x;
        colT[p1] = s4.y;
        colT[p2] = s4.z;
        colT[p3] = s4.w;
    }
}

// ---------------- fold attention weights + transpose W2 (merged) ----------------
__global__ void paramwt_kernel(const float* __restrict__ W1, const float* __restrict__ as1,
                               const float* __restrict__ ad1,
                               const float* __restrict__ W2, const float* __restrict__ as2,
                               const float* __restrict__ ad2){
    int i = blockIdx.x*blockDim.x + threadIdx.x;
    if (i >= NT*HID*HID) return;
    int t = i >> 10;
    int r = i & 1023;
    int f = r >> 5, j = r & 31;
    const float* wb = W2 + (t*HID + f)*128 + j;
    g_Wt[i] = make_float4(wb[0], wb[32], wb[64], wb[96]);
    if (j < 4){
        int h = j;
        float sa = 0.f, sd = 0.f;
        const float* wrow = W2 + (t*HID + f)*128 + h*32;
        const float* arow = as2 + (t*4 + h)*32;
        const float* drow = ad2 + (t*4 + h)*32;
        #pragma unroll
        for (int c = 0; c < 32; c++){ sa += wrow[c]*arow[c]; sd += wrow[c]*drow[c]; }
        ((float*)g_As2)[(t*HID + f)*4 + h] = sa;
        ((float*)g_Ad2)[(t*HID + f)*4 + h] = sd;
        if (f == 0){
            float s1 = 0.f, d1 = 0.f;
            const float* w1 = W1 + t*128 + h*32;
            const float* a1 = as1 + (t*4 + h)*32;
            const float* dd1 = ad1 + (t*4 + h)*32;
            #pragma unroll
            for (int c = 0; c < 32; c++){ s1 += w1[c]*a1[c]; d1 += w1[c]*dd1[c]; }
            ((float*)g_SA)[t*4 + h] = s1;
            ((float*)g_DA)[t*4 + h] = d1;
        }
    }
}

// ---------------- layer-1 edge aggregation: thread per (type,dst) ----------------
__global__ void l1_edge_kernel(const float* __restrict__ x){
    int i = blockIdx.x*blockDim.x + threadIdx.x;
    if (i >= NT*NN) return;
    int t = i / NN, n = i - t*NN;
    float4 SAv = g_SA[t];
    float4 DAv = g_DA[t];
    float SA[4] = {SAv.x, SAv.y, SAv.z, SAv.w};
    float DA[4] = {DAv.x, DAv.y, DAv.z, DAv.w};
    float xd = x[c_dst[t]*NN + n];
    float dsc[4];
    #pragma unroll
    for (int h = 0; h < 4; h++) dsc[h] = xd * DA[h];
    const float* xs = x + c_src[t]*NN;
    const int* col = g_col + t*NE;
    int beg = g_off[t*(NN+1) + n];
    int end = g_off[t*(NN+1) + n + 1];
    float den[4] = {0,0,0,0}, acc[4] = {0,0,0,0};
    for (int j = beg; j < end; j++){
        int s = col[j];
        float xv = xs[s];
        #pragma unroll
        for (int h = 0; h < 4; h++){
            float p = __expf(lrelu(xv*SA[h] + dsc[h]));
            den[h] += p;
            acc[h] += p*xv;
        }
    }
    float4 z;
    z.x = den[0] > 0.f ? acc[0]/den[0] : 0.f;
    z.y = den[1] > 0.f ? acc[1]/den[1] : 0.f;
    z.z = den[2] > 0.f ? acc[2]/den[2] : 0.f;
    z.w = den[3] > 0.f ? acc[3]/den[3] : 0.f;
    g_za[t*NN + n] = z;
}

// ---------------- layer-1 combine + layer-2 scores (fused, warp per node) ----------------
// warp (c,n): lane j computes y[c][n][j] (rank-1 expansion + hetero mean + relu),
// then the 8 score dot-products for this node (4 types with src==c -> s2,
// 4 types with dst==c -> d2) via float4 butterfly reductions.
__global__ void l1cs_kernel(const float* __restrict__ W1, const float* __restrict__ b1){
    int wg = blockIdx.x*8 + (threadIdx.x >> 5);
    if (wg >= NCH*NN) return;
    int lane = threadIdx.x & 31;
    int c = wg / NN, n = wg - c*NN;
    int j = lane;
    float v = 0.f;
    #pragma unroll
    for (int k = 0; k < 4; k++){
        int t = c_in[c][k];
        float4 za = g_za[t*NN + n];
        const float* w = W1 + t*128;
        float o = za.x*w[j] + za.y*w[32+j] + za.z*w[64+j] + za.w*w[96+j];
        v += o*0.25f + b1[t*HID + j];
    }
    v *= 0.25f;                       // hetero mean over 4 incoming types
    v = v > 0.f ? v : 0.f;
    g_y[c*NN*HID + n*HID + j] = v;
    #pragma unroll
    for (int k = 0; k < 4; k++){
        int ts = c_out[c][k];         // this node is src for these types
        float4 a = g_As2[ts*HID + j];
        float4 s = make_float4(v*a.x, v*a.y, v*a.z, v*a.w);
        int td = c_in[c][k];          // this node is dst for these types
        float4 bq = g_Ad2[td*HID + j];
        float4 d = make_float4(v*bq.x, v*bq.y, v*bq.z, v*bq.w);
        #pragma unroll
        for (int o2 = 16; o2; o2 >>= 1){
            s.x += __shfl_xor_sync(0xffffffffu, s.x, o2);
            s.y += __shfl_xor_sync(0xffffffffu, s.y, o2);
            s.z += __shfl_xor_sync(0xffffffffu, s.z, o2);
            s.w += __shfl_xor_sync(0xffffffffu, s.w, o2);
            d.x += __shfl_xor_sync(0xffffffffu, d.x, o2);
            d.y += __shfl_xor_sync(0xffffffffu, d.y, o2);
            d.z += __shfl_xor_sync(0xffffffffu, d.z, o2);
            d.w += __shfl_xor_sync(0xffffffffu, d.w, o2);
        }
        if (lane == 0){
            g_s2[ts*NN + n] = s;
            g_d2[td*NN + n] = d;
        }
    }
}

// ---------------- layer-2 fused: softmax + gather + block-GEMM epilogue ----------------
// Phase 1 (warp per dst node, 4 types): lane-parallel exp into per-warp smem
// p-tiles, warp-reduce den, serial y-row gather with packed f32x2 FMAs,
// normalize once, stage z into zsm[k][n][f].
// Phase 2 (block GEMM): Out[32n][32j] = sum_k Z_k * Wt_k, 2x2 register tiles,
// k split over 4 thread groups; Wt read directly from L1-resident g_Wt.
__global__ void __launch_bounds__(1024) l2_gather_kernel(const float* __restrict__ b2,
                                                         float* __restrict__ out){
    extern __shared__ float smemf[];
    float4* zsm = (float4*)smemf;                 // [4][32n][32f] f4(h): 64 KB
    float4* wbA = (float4*)(smemf + 16384);       // [32 warps][CAP]:     32 KB
    int*    cbA = (int*)  (smemf + 24576);        // [32 warps][CAP]:      8 KB
    float*  psum = (float*)wbA;                   // reused in phase 2:   16 KB
    int c = blockIdx.y;
    int tid = threadIdx.x;
    int warp = tid >> 5, lane = tid & 31;
    int n = blockIdx.x*32 + warp;                 // grid.x = 625, exact cover
    float4* wb = wbA + warp*CAP;
    int* cb = cbA + warp*CAP;
    #pragma unroll
    for (int k = 0; k < 4; k++){
        int t = c_in[c][k];
        const float* ysrc = g_y + c_src[t]*NN*HID;
        const int* col = g_col + t*NE;
        const float4* s2 = g_s2 + t*NN;
        int beg = g_off[t*(NN+1) + n], end = g_off[t*(NN+1) + n + 1];
        int deg = end - beg;
        float4 dv = g_d2[t*NN + n];
        float d0 = 0.f, d1 = 0.f, d2 = 0.f, d3 = 0.f;
        unsigned long long a01 = 0ull, a23 = 0ull;
        if (deg <= CAP){
            for (int base = 0; base < deg; base += 32){
                int j = base + lane;
                if (j < deg){
                    int s = col[beg + j];
                    float4 sv = s2[s];
                    float4 p;
                    p.x = __expf(lrelu(sv.x + dv.x));
                    p.y = __expf(lrelu(sv.y + dv.y));
                    p.z = __expf(lrelu(sv.z + dv.z));
                    p.w = __expf(lrelu(sv.w + dv.w));
                    d0 += p.x; d1 += p.y; d2 += p.z; d3 += p.w;
                    wb[j] = p; cb[j] = s;
                }
            }
            __syncwarp();
            #pragma unroll
            for (int o = 16; o; o >>= 1){
                d0 += __shfl_xor_sync(0xffffffffu, d0, o);
                d1 += __shfl_xor_sync(0xffffffffu, d1, o);
                d2 += __shfl_xor_sync(0xffffffffu, d2, o);
                d3 += __shfl_xor_sync(0xffffffffu, d3, o);
            }
            int i = 0;
            for (; i + 1 < deg; i += 2){        // ILP2 on the y-row gather
                ulonglong2 pw0 = *(const ulonglong2*)(wb + i);
                ulonglong2 pw1 = *(const ulonglong2*)(wb + i + 1);
                int s0 = cb[i], s1 = cb[i+1];
                float y0 = ysrc[s0*HID + lane];
                float y1 = ysrc[s1*HID + lane];
                unsigned long long y20 = pk2(y0, y0);
                unsigned long long y21 = pk2(y1, y1);
                fma2(a01, pw0.x, y20); fma2(a23, pw0.y, y20);
                fma2(a01, pw1.x, y21); fma2(a23, pw1.y, y21);
            }
            if (i < deg){
                ulonglong2 pw = *(const ulonglong2*)(wb + i);
                float yv = ysrc[cb[i]*HID + lane];
                unsigned long long y2 = pk2(yv, yv);
                fma2(a01, pw.x, y2); fma2(a23, pw.y, y2);
            }
            __syncwarp();
        } else {                                  // rare fallback: recompute path
            for (int base = beg; base < end; base += 32){
                int j = base + lane;
                if (j < end){
                    int s = col[j];
                    float4 sv = s2[s];
                    d0 += __expf(lrelu(sv.x + dv.x));
                    d1 += __expf(lrelu(sv.y + dv.y));
                    d2 += __expf(lrelu(sv.z + dv.z));
                    d3 += __expf(lrelu(sv.w + dv.w));
                }
            }
            #pragma unroll
            for (int o = 16; o; o >>= 1){
                d0 += __shfl_xor_sync(0xffffffffu, d0, o);
                d1 += __shfl_xor_sync(0xffffffffu, d1, o);
                d2 += __shfl_xor_sync(0xffffffffu, d2, o);
                d3 += __shfl_xor_sync(0xffffffffu, d3, o);
            }
            for (int base = beg; base < end; base += 32){
                int j = base + lane;
                int m = min(32, end - base);
                if (j < end){
                    int s = col[j];
                    float4 sv = s2[s];
                    float4 p;
                    p.x = __expf(lrelu(sv.x + dv.x));
                    p.y = __expf(lrelu(sv.y + dv.y));
                    p.z = __expf(lrelu(sv.z + dv.z));
                    p.w = __expf(lrelu(sv.w + dv.w));
                    wb[lane] = p; cb[lane] = s;
                }
                __syncwarp();
                for (int i = 0; i < m; i++){
                    ulonglong2 pw = *(const ulonglong2*)(wb + i);
                    float yv = ysrc[cb[i]*HID + lane];
                    unsigned long long y2 = pk2(yv, yv);
                    fma2(a01, pw.x, y2); fma2(a23, pw.y, y2);
                }
                __syncwarp();
            }
        }
        unsigned long long r01 = pk2(d0 > 0.f ? __fdividef(0.25f, d0) : 0.f,
                                     d1 > 0.f ? __fdividef(0.25f, d1) : 0.f);
        unsigned long long r23 = pk2(d2 > 0.f ? __fdividef(0.25f, d2) : 0.f,
                                     d3 > 0.f ? __fdividef(0.25f, d3) : 0.f);
        mul2(a01, a01, r01);
        mul2(a23, a23, r23);
        *(ulonglong2*)(zsm + (k*32 + warp)*32 + lane) = make_ulonglong2(a01, a23);
    }
    __syncthreads();
    // phase 2: block GEMM, 2x2 tiles, k split over thread groups; Wt from L1
    {
        int g  = tid >> 8;            // k
        int r  = tid & 255;
        int tn = r >> 4;              // 0..15
        int tj = r & 15;              // 0..15
        const float4* Zk = zsm + g*1024;
        const float4* Wk = g_Wt + c_in[c][g]*1024;
        unsigned long long aA00=0ull, aB00=0ull, aA01=0ull, aB01=0ull;
        unsigned long long aA10=0ull, aB10=0ull, aA11=0ull, aB11=0ull;
        #pragma unroll 4
        for (int f = 0; f < 32; f++){
            ulonglong2 z0 = *(const ulonglong2*)(Zk + tn*32 + f);
            ulonglong2 z1 = *(const ulonglong2*)(Zk + (tn+16)*32 + f);
            ulonglong2 w0 = *(const ulonglong2*)(Wk + f*32 + tj);
            ulonglong2 w1 = *(const ulonglong2*)(Wk + f*32 + tj + 16);
            fma2(aA00, z0.x, w0.x); fma2(aB00, z0.y, w0.y);
            fma2(aA01, z0.x, w1.x); fma2(aB01, z0.y, w1.y);
            fma2(aA10, z1.x, w0.x); fma2(aB10, z1.y, w0.y);
            fma2(aA11, z1.x, w1.x); fma2(aB11, z1.y, w1.y);
        }
        float2 A, B;
        A = upk2(aA00); B = upk2(aB00);
        psum[(g*32 + tn   )*32 + tj   ] = A.x + A.y + B.x + B.y;
        A = upk2(aA01); B = upk2(aB01);
        psum[(g*32 + tn   )*32 + tj+16] = A.x + A.y + B.x + B.y;
        A = upk2(aA10); B = upk2(aB10);
        psum[(g*32 + tn+16)*32 + tj   ] = A.x + A.y + B.x + B.y;
        A = upk2(aA11); B = upk2(aB11);
        psum[(g*32 + tn+16)*32 + tj+16] = A.x + A.y + B.x + B.y;
    }
    __syncthreads();
    {
        int nn = tid >> 5, j = tid & 31;
        float o = psum[nn*32 + j] + psum[1024 + nn*32 + j]
                + psum[2048 + nn*32 + j] + psum[3072 + nn*32 + j];
        float bs = b2[c_in[c][0]*HID + j] + b2[c_in[c][1]*HID + j]
                 + b2[c_in[c][2]*HID + j] + b2[c_in[c][3]*HID + j];
        float v = (o + bs)*0.25f;     // hetero mean over 4 types
        int ng = blockIdx.x*32 + nn;
        out[ng*(NCH*HID) + c*HID + j] = v > 0.f ? v : 0.f;
    }
}

extern "C" void kernel_launch(void* const* d_in, const int* in_sizes, int n_in,
                              void* d_out, int out_size){
    const float* x   = (const float*)d_in[0];
    const int*   edg = (const int*)  d_in[1];
    const float* W1  = (const float*)d_in[2];
    const float* as1 = (const float*)d_in[3];
    const float* ad1 = (const float*)d_in[4];
    const float* b1  = (const float*)d_in[5];
    const float* W2  = (const float*)d_in[6];
    const float* as2 = (const float*)d_in[7];
    const float* ad2 = (const float*)d_in[8];
    const float* b2  = (const float*)d_in[9];
    float* out = (float*)d_out;

    static bool attr_set = false;
    if (!attr_set){
        cudaFuncSetAttribute(l2_gather_kernel,
                             cudaFuncAttributeMaxDynamicSharedMemorySize, 106496);
        cudaFuncSetAttribute(count_kernel,
                             cudaFuncAttributeMaxDynamicSharedMemorySize, NN*4);
        cudaFuncSetAttribute(fill_kernel,
                             cudaFuncAttributeMaxDynamicSharedMemorySize, NN*4);
        attr_set = true;
    }

    count_kernel<<<NT*NBLK, 1024, NN*4>>>(edg);
    pprefix_kernel<<<(NT*NN + 255)/256, 256>>>();
    paramwt_kernel<<<(NT*HID*HID + 255)/256, 256>>>(W1, as1, ad1, W2, as2, ad2);
    scanA_kernel<<<NT*NCHK, 256>>>();
    scanB_kernel<<<1, 32>>>();
    scanC_kernel<<<NT*NCHK, 256>>>();
    fill_kernel<<<NT*NBLK, 1024, NN*4>>>(edg);
    l1_edge_kernel<<<(NT*NN + 255)/256, 256>>>(x);
    l1cs_kernel<<<(NCH*NN + 7)/8, 256>>>(W1, b1);
    dim3 g2(NN/32, NCH);   // 625 x 4
    l2_gather_kernel<<<g2, 1024, 106496>>>(b2, out);
}

// round 10
// speedup vs baseline: 2.0341x; 1.0563x over previous
#include <cuda_runtime.h>
#include <math.h>

#define NCH 4
#define NN 20000
#define NE 320000
#define NT 16
#define HID 32
#define CHUNK 2048
#define NCHK 10    // ceil(20000/2048)
#define CAP 64     // per-warp p-tile capacity in l2_gather
#define NBLK 8     // histogram blocks per edge type
#define SL (NE/NBLK)

// edge-type metadata: 4 spatial (c->c) then 12 inter-channel (s!=d)
__constant__ int c_src[16] = {0,1,2,3, 0,0,0, 1,1,1, 2,2,2, 3,3,3};
__constant__ int c_dst[16] = {0,1,2,3, 1,2,3, 0,2,3, 0,1,3, 0,1,2};
__constant__ int c_in[4][4]  = {{0,7,10,13},{1,4,11,14},{2,5,8,15},{3,6,9,12}};  // dst==c
__constant__ int c_out[4][4] = {{0,4,5,6},{1,7,8,9},{2,10,11,12},{3,13,14,15}};  // src==c

// scratch (static device globals; no allocation)
__device__ int    g_pc[NT*NBLK*NN];     // per-(type,block) partial counts -> prefixes
__device__ int    g_cnt[NT*NN];         // per-(type,node) total counts
__device__ int    g_off[NT*(NN+1)];
__device__ int    g_rank[NT*NE];        // per-edge local rank within its count block
__device__ int    g_col[NT*NE];
__device__ int    g_bsum[NT*NCHK];
__device__ float4 g_za[NT*NN];          // layer1 per-(type,dst) head aggregates
__device__ float  g_y[NCH*NN*HID];      // layer1 output (post relu)
__device__ float4 g_s2[NT*NN];          // layer2 src scores per head
__device__ float4 g_d2[NT*NN];          // layer2 dst scores per head
__device__ float4 g_As2[NT*HID];        // W2^T @ att_src2 folded: [t][f][h]
__device__ float4 g_Ad2[NT*HID];
__device__ float4 g_SA[NT];             // layer1 folded score weights [t][h]
__device__ float4 g_DA[NT];
__device__ float4 g_Wt[NT*HID*HID];     // W2 transposed: [t][f][j] = {W2[t][f][h*32+j]}_h

__device__ __forceinline__ float lrelu(float v){ return v > 0.f ? v : 0.2f*v; }

// ---- packed f32x2 helpers (sm_103a) ----
__device__ __forceinline__ unsigned long long pk2(float lo, float hi){
    unsigned long long r;
    asm("mov.b64 %0, {%1, %2};" : "=l"(r) : "f"(lo), "f"(hi));
    return r;
}
__device__ __forceinline__ void fma2(unsigned long long& d, unsigned long long a,
                                     unsigned long long b){
    asm("fma.rn.f32x2 %0, %1, %2, %3;" : "=l"(d) : "l"(a), "l"(b), "l"(d));
}
__device__ __forceinline__ void mul2(unsigned long long& d, unsigned long long a,
                                     unsigned long long b){
    asm("mul.rn.f32x2 %0, %1, %2;" : "=l"(d) : "l"(a), "l"(b));
}
__device__ __forceinline__ void add2(unsigned long long& d, unsigned long long a,
                                     unsigned long long b){
    asm("add.rn.f32x2 %0, %1, %2;" : "=l"(d) : "l"(a), "l"(b));
}
__device__ __forceinline__ float2 upk2(unsigned long long v){
    float2 r;
    asm("mov.b64 {%0, %1}, %2;" : "=f"(r.x), "=f"(r.y) : "l"(v));
    return r;
}

// ---------------- CSR: smem histogram count + per-edge rank (one atomic pass) ----
__global__ void __launch_bounds__(1024) countrank_kernel(const int* __restrict__ edges){
    extern __shared__ int hist[];           // [NN] = 80 KB
    int b = blockIdx.x;                     // b = t*NBLK + blk
    int t = b >> 3, blk = b & 7;
    for (int i = threadIdx.x; i < NN; i += 1024) hist[i] = 0;
    __syncthreads();
    const int4* dstp = (const int4*)(edges + t*2*NE + NE + blk*SL);
    int4* rnkp = (int4*)(g_rank + t*NE + blk*SL);
    for (int i = threadIdx.x; i < SL/4; i += 1024){
        int4 d4 = dstp[i];
        int4 r;
        r.x = atomicAdd(&hist[d4.x], 1);
        r.y = atomicAdd(&hist[d4.y], 1);
        r.z = atomicAdd(&hist[d4.z], 1);
        r.w = atomicAdd(&hist[d4.w], 1);
        rnkp[i] = r;
    }
    __syncthreads();
    int* pc = g_pc + b*NN;
    for (int i = threadIdx.x; i < NN; i += 1024) pc[i] = hist[i];
}

// ---------------- merged: per-node prefix over NBLK partials + chunk sums ------
// thread owns 8 consecutive nodes; all g_pc traffic is int4-coalesced.
__global__ void __launch_bounds__(256) prefA_kernel(){
    __shared__ int sd[256];
    int b = blockIdx.x;                     // b = t*NCHK + chunk
    int t = b / NCHK, chunk = b % NCHK;
    int tid = threadIdx.x;
    int base = chunk*CHUNK + tid*8;         // NN%8==0 -> base<NN implies base+8<=NN
    int v[NBLK][8];
    bool ok = base < NN;
    #pragma unroll
    for (int k = 0; k < NBLK; k++){
        int4 a = make_int4(0,0,0,0), c4 = make_int4(0,0,0,0);
        if (ok){
            const int4* p = (const int4*)(g_pc + (t*NBLK + k)*NN + base);
            a = p[0]; c4 = p[1];
        }
        v[k][0]=a.x; v[k][1]=a.y; v[k][2]=a.z; v[k][3]=a.w;
        v[k][4]=c4.x; v[k][5]=c4.y; v[k][6]=c4.z; v[k][7]=c4.w;
    }
    int cnt[8];
    int tsum = 0;
    #pragma unroll
    for (int e = 0; e < 8; e++){
        int run = 0;
        #pragma unroll
        for (int k = 0; k < NBLK; k++){
            int tmp = v[k][e];
            v[k][e] = run;                  // exclusive prefix across blocks
            run += tmp;
        }
        cnt[e] = run;
        tsum += run;
    }
    if (ok){
        #pragma unroll
        for (int k = 0; k < NBLK; k++){
            int4* p = (int4*)(g_pc + (t*NBLK + k)*NN + base);
            p[0] = make_int4(v[k][0], v[k][1], v[k][2], v[k][3]);
            p[1] = make_int4(v[k][4], v[k][5], v[k][6], v[k][7]);
        }
        int4* cp = (int4*)(g_cnt + t*NN + base);
        cp[0] = make_int4(cnt[0], cnt[1], cnt[2], cnt[3]);
        cp[1] = make_int4(cnt[4], cnt[5], cnt[6], cnt[7]);
    }
    sd[tid] = tsum;
    __syncthreads();
    #pragma unroll
    for (int ofs = 128; ofs > 0; ofs >>= 1){
        if (tid < ofs) sd[tid] += sd[tid+ofs];
        __syncthreads();
    }
    if (tid == 0) g_bsum[b] = sd[0];
}

// ---------------- scan: per-chunk exclusive scan -> g_off (bbase inline) -------
__global__ void __launch_bounds__(256) scanC_kernel(){
    __shared__ int sd[256];
    __shared__ int bb;
    int b = blockIdx.x;
    int t = b / NCHK, chunk = b % NCHK;
    int tid = threadIdx.x;
    if (tid == 0){
        int run = 0;
        for (int k = 0; k < chunk; k++) run += g_bsum[t*NCHK + k];
        bb = run;
        if (chunk == 0) g_off[t*(NN+1)] = 0;
    }
    int base = chunk*CHUNK + tid*8;
    int c[8];
    int tsum = 0;
    bool ok = base < NN;
    {
        int4 a = make_int4(0,0,0,0), d = make_int4(0,0,0,0);
        if (ok){
            const int4* p = (const int4*)(g_cnt + t*NN + base);
            a = p[0]; d = p[1];
        }
        c[0]=a.x; c[1]=a.y; c[2]=a.z; c[3]=a.w;
        c[4]=d.x; c[5]=d.y; c[6]=d.z; c[7]=d.w;
        #pragma unroll
        for (int e = 0; e < 8; e++) tsum += c[e];
    }
    sd[tid] = tsum;
    __syncthreads();
    #pragma unroll
    for (int ofs = 1; ofs < 256; ofs <<= 1){
        int add = (tid >= ofs) ? sd[tid-ofs] : 0;
        __syncthreads();
        sd[tid] += add;
        __syncthreads();
    }
    int run = sd[tid] - tsum + bb;
    if (ok){
        #pragma unroll
        for (int e = 0; e < 8; e++){
            run += c[e];
            g_off[t*(NN+1) + base + e + 1] = run;
        }
    }
}

// ---------------- CSR: fill, atomic-free (smem cursor table + stored ranks) ----
__global__ void __launch_bounds__(1024) fill2_kernel(const int* __restrict__ edges){
    extern __shared__ int cur[];            // [NN] = 80 KB
    int b = blockIdx.x;
    int t = b >> 3, blk = b & 7;
    const int* offT = g_off + t*(NN+1);
    const int* pc = g_pc + b*NN;
    for (int i = threadIdx.x; i < NN; i += 1024) cur[i] = offT[i] + pc[i];
    __syncthreads();
    const int4* srcp = (const int4*)(edges + t*2*NE + blk*SL);
    const int4* dstp = (const int4*)(edges + t*2*NE + NE + blk*SL);
    const int4* rnkp = (const int4*)(g_rank + t*NE + blk*SL);
    int* colT = g_col + t*NE;
    for (int i = threadIdx.x; i < SL/4; i += 1024){
        int4 s4 = srcp[i];
        int4 d4 = dstp[i];
        int4 r4 = rnkp[i];
        colT[cur[d4.x] + r4.x] = s4.x;
        colT[cur[d4.y] + r4.y] = s4.y;
        colT[cur[d4.z] + r4.z] = s4.z;
        colT[cur[d4.w] + r4.w] = s4.w;
    }
}

// ---------------- fold attention weights + transpose W2 (merged) ----------------
__global__ void paramwt_kernel(const float* __restrict__ W1, const float* __restrict__ as1,
                               const float* __restrict__ ad1,
                               const float* __restrict__ W2, const float* __restrict__ as2,
                               const float* __restrict__ ad2){
    int i = blockIdx.x*blockDim.x + threadIdx.x;
    if (i >= NT*HID*HID) return;
    int t = i >> 10;
    int r = i & 1023;
    int f = r >> 5, j = r & 31;
    const float* wb = W2 + (t*HID + f)*128 + j;
    g_Wt[i] = make_float4(wb[0], wb[32], wb[64], wb[96]);
    if (j < 4){
        int h = j;
        float sa = 0.f, sd = 0.f;
        const float* wrow = W2 + (t*HID + f)*128 + h*32;
        const float* arow = as2 + (t*4 + h)*32;
        const float* drow = ad2 + (t*4 + h)*32;
        #pragma unroll
        for (int c = 0; c < 32; c++){ sa += wrow[c]*arow[c]; sd += wrow[c]*drow[c]; }
        ((float*)g_As2)[(t*HID + f)*4 + h] = sa;
        ((float*)g_Ad2)[(t*HID + f)*4 + h] = sd;
        if (f == 0){
            float s1 = 0.f, d1 = 0.f;
            const float* w1 = W1 + t*128 + h*32;
            const float* a1 = as1 + (t*4 + h)*32;
            const float* dd1 = ad1 + (t*4 + h)*32;
            #pragma unroll
            for (int c = 0; c < 32; c++){ s1 += w1[c]*a1[c]; d1 += w1[c]*dd1[c]; }
            ((float*)g_SA)[t*4 + h] = s1;
            ((float*)g_DA)[t*4 + h] = d1;
        }
    }
}

// ---------------- layer-1 edge aggregation: thread per (type,dst) ----------------
__global__ void l1_edge_kernel(const float* __restrict__ x){
    int i = blockIdx.x*blockDim.x + threadIdx.x;
    if (i >= NT*NN) return;
    int t = i / NN, n = i - t*NN;
    float4 SAv = g_SA[t];
    float4 DAv = g_DA[t];
    float SA[4] = {SAv.x, SAv.y, SAv.z, SAv.w};
    float DA[4] = {DAv.x, DAv.y, DAv.z, DAv.w};
    float xd = x[c_dst[t]*NN + n];
    float dsc[4];
    #pragma unroll
    for (int h = 0; h < 4; h++) dsc[h] = xd * DA[h];
    const float* xs = x + c_src[t]*NN;
    const int* col = g_col + t*NE;
    int beg = g_off[t*(NN+1) + n];
    int end = g_off[t*(NN+1) + n + 1];
    float den[4] = {0,0,0,0}, acc[4] = {0,0,0,0};
    for (int j = beg; j < end; j++){
        int s = col[j];
        float xv = xs[s];
        #pragma unroll
        for (int h = 0; h < 4; h++){
            float p = __expf(lrelu(xv*SA[h] + dsc[h]));
            den[h] += p;
            acc[h] += p*xv;
        }
    }
    float4 z;
    z.x = den[0] > 0.f ? acc[0]/den[0] : 0.f;
    z.y = den[1] > 0.f ? acc[1]/den[1] : 0.f;
    z.z = den[2] > 0.f ? acc[2]/den[2] : 0.f;
    z.w = den[3] > 0.f ? acc[3]/den[3] : 0.f;
    g_za[t*NN + n] = z;
}

// ---------------- layer-1 combine + layer-2 scores (fused, warp per node) -------
__global__ void l1cs_kernel(const float* __restrict__ W1, const float* __restrict__ b1){
    int wg = blockIdx.x*8 + (threadIdx.x >> 5);
    if (wg >= NCH*NN) return;
    int lane = threadIdx.x & 31;
    int c = wg / NN, n = wg - c*NN;
    int j = lane;
    float v = 0.f;
    #pragma unroll
    for (int k = 0; k < 4; k++){
        int t = c_in[c][k];
        float4 za = g_za[t*NN + n];
        const float* w = W1 + t*128;
        float o = za.x*w[j] + za.y*w[32+j] + za.z*w[64+j] + za.w*w[96+j];
        v += o*0.25f + b1[t*HID + j];
    }
    v *= 0.25f;                       // hetero mean over 4 incoming types
    v = v > 0.f ? v : 0.f;
    g_y[c*NN*HID + n*HID + j] = v;
    #pragma unroll
    for (int k = 0; k < 4; k++){
        int ts = c_out[c][k];         // this node is src for these types
        float4 a = g_As2[ts*HID + j];
        float4 s = make_float4(v*a.x, v*a.y, v*a.z, v*a.w);
        int td = c_in[c][k];          // this node is dst for these types
        float4 bq = g_Ad2[td*HID + j];
        float4 d = make_float4(v*bq.x, v*bq.y, v*bq.z, v*bq.w);
        #pragma unroll
        for (int o2 = 16; o2; o2 >>= 1){
            s.x += __shfl_xor_sync(0xffffffffu, s.x, o2);
            s.y += __shfl_xor_sync(0xffffffffu, s.y, o2);
            s.z += __shfl_xor_sync(0xffffffffu, s.z, o2);
            s.w += __shfl_xor_sync(0xffffffffu, s.w, o2);
            d.x += __shfl_xor_sync(0xffffffffu, d.x, o2);
            d.y += __shfl_xor_sync(0xffffffffu, d.y, o2);
            d.z += __shfl_xor_sync(0xffffffffu, d.z, o2);
            d.w += __shfl_xor_sync(0xffffffffu, d.w, o2);
        }
        if (lane == 0){
            g_s2[ts*NN + n] = s;
            g_d2[td*NN + n] = d;
        }
    }
}

// ---------------- layer-2 fused: softmax + gather + block-GEMM epilogue ----------
__global__ void __launch_bounds__(1024) l2_gather_kernel(const float* __restrict__ b2,
                                                         float* __restrict__ out){
    extern __shared__ float smemf[];
    float4* zsm = (float4*)smemf;                 // [4][32n][32f] f4(h): 64 KB
    float4* wbA = (float4*)(smemf + 16384);       // [32 warps][CAP]:     32 KB
    int*    cbA = (int*)  (smemf + 24576);        // [32 warps][CAP]:      8 KB
    float*  psum = (float*)wbA;                   // reused in phase 2:   16 KB
    int c = blockIdx.y;
    int tid = threadIdx.x;
    int warp = tid >> 5, lane = tid & 31;
    int n = blockIdx.x*32 + warp;                 // grid.x = 625, exact cover
    float4* wb = wbA + warp*CAP;
    int* cb = cbA + warp*CAP;
    #pragma unroll
    for (int k = 0; k < 4; k++){
        int t = c_in[c][k];
        const float* ysrc = g_y + c_src[t]*NN*HID;
        const int* col = g_col + t*NE;
        const float4* s2 = g_s2 + t*NN;
        int beg = g_off[t*(NN+1) + n], end = g_off[t*(NN+1) + n + 1];
        int deg = end - beg;
        float4 dv = g_d2[t*NN + n];
        float d0 = 0.f, d1 = 0.f, d2 = 0.f, d3 = 0.f;
        unsigned long long a01 = 0ull, a23 = 0ull;
        unsigned long long b01 = 0ull, b23 = 0ull;
        if (deg <= CAP){
            for (int base = 0; base < deg; base += 32){
                int j = base + lane;
                if (j < deg){
                    int s = col[beg + j];
                    float4 sv = s2[s];
                    float4 p;
                    p.x = __expf(lrelu(sv.x + dv.x));
                    p.y = __expf(lrelu(sv.y + dv.y));
                    p.z = __expf(lrelu(sv.z + dv.z));
                    p.w = __expf(lrelu(sv.w + dv.w));
                    d0 += p.x; d1 += p.y; d2 += p.z; d3 += p.w;
                    wb[j] = p; cb[j] = s;
                }
            }
            __syncwarp();
            #pragma unroll
            for (int o = 16; o; o >>= 1){
                d0 += __shfl_xor_sync(0xffffffffu, d0, o);
                d1 += __shfl_xor_sync(0xffffffffu, d1, o);
                d2 += __shfl_xor_sync(0xffffffffu, d2, o);
                d3 += __shfl_xor_sync(0xffffffffu, d3, o);
            }
            int i = 0;
            for (; i + 3 < deg; i += 4){        // ILP4 on the y-row gather
                int s0 = cb[i], s1 = cb[i+1], s2i = cb[i+2], s3 = cb[i+3];
                float y0 = ysrc[s0*HID + lane];
                float y1 = ysrc[s1*HID + lane];
                float y2 = ysrc[s2i*HID + lane];
                float y3 = ysrc[s3*HID + lane];
                ulonglong2 pw0 = *(const ulonglong2*)(wb + i);
                ulonglong2 pw1 = *(const ulonglong2*)(wb + i + 1);
                ulonglong2 pw2 = *(const ulonglong2*)(wb + i + 2);
                ulonglong2 pw3 = *(const ulonglong2*)(wb + i + 3);
                unsigned long long y20 = pk2(y0, y0);
                unsigned long long y21 = pk2(y1, y1);
                unsigned long long y22 = pk2(y2, y2);
                unsigned long long y23 = pk2(y3, y3);
                fma2(a01, pw0.x, y20); fma2(a23, pw0.y, y20);
                fma2(b01, pw1.x, y21); fma2(b23, pw1.y, y21);
                fma2(a01, pw2.x, y22); fma2(a23, pw2.y, y22);
                fma2(b01, pw3.x, y23); fma2(b23, pw3.y, y23);
            }
            for (; i < deg; i++){
                ulonglong2 pw = *(const ulonglong2*)(wb + i);
                float yv = ysrc[cb[i]*HID + lane];
                unsigned long long y2 = pk2(yv, yv);
                fma2(a01, pw.x, y2); fma2(a23, pw.y, y2);
            }
            add2(a01, a01, b01);
            add2(a23, a23, b23);
            __syncwarp();
        } else {                                  // rare fallback: recompute path
            for (int base = beg; base < end; base += 32){
                int j = base + lane;
                if (j < end){
                    int s = col[j];
                    float4 sv = s2[s];
                    d0 += __expf(lrelu(sv.x + dv.x));
                    d1 += __expf(lrelu(sv.y + dv.y));
                    d2 += __expf(lrelu(sv.z + dv.z));
                    d3 += __expf(lrelu(sv.w + dv.w));
                }
            }
            #pragma unroll
            for (int o = 16; o; o >>= 1){
                d0 += __shfl_xor_sync(0xffffffffu, d0, o);
                d1 += __shfl_xor_sync(0xffffffffu, d1, o);
                d2 += __shfl_xor_sync(0xffffffffu, d2, o);
                d3 += __shfl_xor_sync(0xffffffffu, d3, o);
            }
            for (int base = beg; base < end; base += 32){
                int j = base + lane;
                int m = min(32, end - base);
                if (j < end){
                    int s = col[j];
                    float4 sv = s2[s];
                    float4 p;
                    p.x = __expf(lrelu(sv.x + dv.x));
                    p.y = __expf(lrelu(sv.y + dv.y));
                    p.z = __expf(lrelu(sv.z + dv.z));
                    p.w = __expf(lrelu(sv.w + dv.w));
                    wb[lane] = p; cb[lane] = s;
                }
                __syncwarp();
                for (int i = 0; i < m; i++){
                    ulonglong2 pw = *(const ulonglong2*)(wb + i);
                    float yv = ysrc[cb[i]*HID + lane];
                    unsigned long long y2 = pk2(yv, yv);
                    fma2(a01, pw.x, y2); fma2(a23, pw.y, y2);
                }
                __syncwarp();
            }
        }
        unsigned long long r01 = pk2(d0 > 0.f ? __fdividef(0.25f, d0) : 0.f,
                                     d1 > 0.f ? __fdividef(0.25f, d1) : 0.f);
        unsigned long long r23 = pk2(d2 > 0.f ? __fdividef(0.25f, d2) : 0.f,
                                     d3 > 0.f ? __fdividef(0.25f, d3) : 0.f);
        mul2(a01, a01, r01);
        mul2(a23, a23, r23);
        *(ulonglong2*)(zsm + (k*32 + warp)*32 + lane) = make_ulonglong2(a01, a23);
    }
    __syncthreads();
    // phase 2: block GEMM, 2x2 tiles, k split over thread groups; Wt from L1
    {
        int g  = tid >> 8;            // k
        int r  = tid & 255;
        int tn = r >> 4;              // 0..15
        int tj = r & 15;              // 0..15
        const float4* Zk = zsm + g*1024;
        const float4* Wk = g_Wt + c_in[c][g]*1024;
        unsigned long long aA00=0ull, aB00=0ull, aA01=0ull, aB01=0ull;
        unsigned long long aA10=0ull, aB10=0ull, aA11=0ull, aB11=0ull;
        #pragma unroll 4
        for (int f = 0; f < 32; f++){
            ulonglong2 z0 = *(const ulonglong2*)(Zk + tn*32 + f);
            ulonglong2 z1 = *(const ulonglong2*)(Zk + (tn+16)*32 + f);
            ulonglong2 w0 = *(const ulonglong2*)(Wk + f*32 + tj);
            ulonglong2 w1 = *(const ulonglong2*)(Wk + f*32 + tj + 16);
            fma2(aA00, z0.x, w0.x); fma2(aB00, z0.y, w0.y);
            fma2(aA01, z0.x, w1.x); fma2(aB01, z0.y, w1.y);
            fma2(aA10, z1.x, w0.x); fma2(aB10, z1.y, w0.y);
            fma2(aA11, z1.x, w1.x); fma2(aB11, z1.y, w1.y);
        }
        float2 A, B;
        A = upk2(aA00); B = upk2(aB00);
        psum[(g*32 + tn   )*32 + tj   ] = A.x + A.y + B.x + B.y;
        A = upk2(aA01); B = upk2(aB01);
        psum[(g*32 + tn   )*32 + tj+16] = A.x + A.y + B.x + B.y;
        A = upk2(aA10); B = upk2(aB10);
        psum[(g*32 + tn+16)*32 + tj   ] = A.x + A.y + B.x + B.y;
        A = upk2(aA11); B = upk2(aB11);
        psum[(g*32 + tn+16)*32 + tj+16] = A.x + A.y + B.x + B.y;
    }
    __syncthreads();
    {
        int nn = tid >> 5, j = tid & 31;
        float o = psum[nn*32 + j] + psum[1024 + nn*32 + j]
                + psum[2048 + nn*32 + j] + psum[3072 + nn*32 + j];
        float bs = b2[c_in[c][0]*HID + j] + b2[c_in[c][1]*HID + j]
                 + b2[c_in[c][2]*HID + j] + b2[c_in[c][3]*HID + j];
        float v = (o + bs)*0.25f;     // hetero mean over 4 types
        int ng = blockIdx.x*32 + nn;
        out[ng*(NCH*HID) + c*HID + j] = v > 0.f ? v : 0.f;
    }
}

extern "C" void kernel_launch(void* const* d_in, const int* in_sizes, int n_in,
                              void* d_out, int out_size){
    const float* x   = (const float*)d_in[0];
    const int*   edg = (const int*)  d_in[1];
    const float* W1  = (const float*)d_in[2];
    const float* as1 = (const float*)d_in[3];
    const float* ad1 = (const float*)d_in[4];
    const float* b1  = (const float*)d_in[5];
    const float* W2  = (const float*)d_in[6];
    const float* as2 = (const float*)d_in[7];
    const float* ad2 = (const float*)d_in[8];
    const float* b2  = (const float*)d_in[9];
    float* out = (float*)d_out;

    static bool attr_set = false;
    if (!attr_set){
        cudaFuncSetAttribute(l2_gather_kernel,
                             cudaFuncAttributeMaxDynamicSharedMemorySize, 106496);
        cudaFuncSetAttribute(countrank_kernel,
                             cudaFuncAttributeMaxDynamicSharedMemorySize, NN*4);
        cudaFuncSetAttribute(fill2_kernel,
                             cudaFuncAttributeMaxDynamicSharedMemorySize, NN*4);
        attr_set = true;
    }

    countrank_kernel<<<NT*NBLK, 1024, NN*4>>>(edg);   // idx 0
    prefA_kernel<<<NT*NCHK, 256>>>();                 // idx 1
    scanC_kernel<<<NT*NCHK, 256>>>();                 // idx 2
    fill2_kernel<<<NT*NBLK, 1024, NN*4>>>(edg);       // idx 3  <- profiler window
    paramwt_kernel<<<(NT*HID*HID + 255)/256, 256>>>(W1, as1, ad1, W2, as2, ad2);
    l1_edge_kernel<<<(NT*NN + 255)/256, 256>>>(x);
    l1cs_kernel<<<(NCH*NN + 7)/8, 256>>>(W1, b1);
    dim3 g2(NN/32, NCH);   // 625 x 4
    l2_gather_kernel<<<g2, 1024, 106496>>>(b2, out);
}

// round 11
// speedup vs baseline: 2.0682x; 1.0168x over previous
#include <cuda_runtime.h>
#include <math.h>

#define NCH 4
#define NN 20000
#define NE 320000
#define NT 16
#define HID 32
#define CHUNK 2048
#define NCHK 10    // scanC chunks (2048 nodes)
#define PCHUNK 1024
#define NPCH 20    // prefA chunks (1024 nodes)
#define CAP 64     // per-warp p-tile capacity in l2_gather
#define NBLK 16    // histogram blocks per edge type
#define SL (NE/NBLK)

// edge-type metadata: 4 spatial (c->c) then 12 inter-channel (s!=d)
__constant__ int c_src[16] = {0,1,2,3, 0,0,0, 1,1,1, 2,2,2, 3,3,3};
__constant__ int c_dst[16] = {0,1,2,3, 1,2,3, 0,2,3, 0,1,3, 0,1,2};
__constant__ int c_in[4][4]  = {{0,7,10,13},{1,4,11,14},{2,5,8,15},{3,6,9,12}};  // dst==c
__constant__ int c_out[4][4] = {{0,4,5,6},{1,7,8,9},{2,10,11,12},{3,13,14,15}};  // src==c

// scratch (static device globals; no allocation)
__device__ int    g_pc[NT*NBLK*NN];     // per-(type,block) partial counts -> prefixes
__device__ int    g_cnt[NT*NN];         // per-(type,node) total counts
__device__ int    g_off[NT*(NN+1)];
__device__ int    g_rank[NT*NE];        // per-edge local rank within its count block
__device__ int    g_col[NT*NE];
__device__ int    g_bsum[NT*NPCH];
__device__ float4 g_za[NT*NN];          // layer1 per-(type,dst) head aggregates
__device__ float  g_y[NCH*NN*HID];      // layer1 output (post relu)
__device__ float4 g_s2[NT*NN];          // layer2 src scores per head
__device__ float4 g_d2[NT*NN];          // layer2 dst scores per head
__device__ float4 g_As2[NT*HID];        // W2^T @ att_src2 folded: [t][f][h]
__device__ float4 g_Ad2[NT*HID];
__device__ float4 g_SA[NT];             // layer1 folded score weights [t][h]
__device__ float4 g_DA[NT];
__device__ float4 g_Wt[NT*HID*HID];     // W2 transposed: [t][f][j] = {W2[t][f][h*32+j]}_h

__device__ __forceinline__ float lrelu(float v){ return v > 0.f ? v : 0.2f*v; }

// ---- packed f32x2 helpers (sm_103a) ----
__device__ __forceinline__ unsigned long long pk2(float lo, float hi){
    unsigned long long r;
    asm("mov.b64 %0, {%1, %2};" : "=l"(r) : "f"(lo), "f"(hi));
    return r;
}
__device__ __forceinline__ void fma2(unsigned long long& d, unsigned long long a,
                                     unsigned long long b){
    asm("fma.rn.f32x2 %0, %1, %2, %3;" : "=l"(d) : "l"(a), "l"(b), "l"(d));
}
__device__ __forceinline__ void mul2(unsigned long long& d, unsigned long long a,
                                     unsigned long long b){
    asm("mul.rn.f32x2 %0, %1, %2;" : "=l"(d) : "l"(a), "l"(b));
}
__device__ __forceinline__ void add2(unsigned long long& d, unsigned long long a,
                                     unsigned long long b){
    asm("add.rn.f32x2 %0, %1, %2;" : "=l"(d) : "l"(a), "l"(b));
}
__device__ __forceinline__ float2 upk2(unsigned long long v){
    float2 r;
    asm("mov.b64 {%0, %1}, %2;" : "=f"(r.x), "=f"(r.y) : "l"(v));
    return r;
}

// ---------------- CSR: smem histogram count + per-edge rank (one atomic pass) ----
__global__ void __launch_bounds__(1024) countrank_kernel(const int* __restrict__ edges){
    extern __shared__ int hist[];           // [NN] = 80 KB
    int b = blockIdx.x;                     // b = t*NBLK + blk
    int t = b >> 4, blk = b & 15;
    for (int i = threadIdx.x; i < NN; i += 1024) hist[i] = 0;
    __syncthreads();
    const int4* dstp = (const int4*)(edges + t*2*NE + NE + blk*SL);
    int4* rnkp = (int4*)(g_rank + t*NE + blk*SL);
    for (int i = threadIdx.x; i < SL/8; i += 1024){
        int4 dA = dstp[2*i];
        int4 dB = dstp[2*i+1];
        int4 rA, rB;
        rA.x = atomicAdd(&hist[dA.x], 1);
        rA.y = atomicAdd(&hist[dA.y], 1);
        rA.z = atomicAdd(&hist[dA.z], 1);
        rA.w = atomicAdd(&hist[dA.w], 1);
        rB.x = atomicAdd(&hist[dB.x], 1);
        rB.y = atomicAdd(&hist[dB.y], 1);
        rB.z = atomicAdd(&hist[dB.z], 1);
        rB.w = atomicAdd(&hist[dB.w], 1);
        rnkp[2*i]   = rA;
        rnkp[2*i+1] = rB;
    }
    __syncthreads();
    int* pc = g_pc + b*NN;
    for (int i = threadIdx.x; i < NN; i += 1024) pc[i] = hist[i];
}

// ---------------- merged: per-node prefix over NBLK partials + chunk sums ------
// thread owns 4 consecutive nodes; all g_pc traffic is int4-coalesced.
__global__ void __launch_bounds__(256) prefA_kernel(){
    __shared__ int sd[256];
    int b = blockIdx.x;                     // b = t*NPCH + chunk
    int t = b / NPCH, chunk = b % NPCH;
    int tid = threadIdx.x;
    int base = chunk*PCHUNK + tid*4;        // NN%4==0 -> base<NN implies base+4<=NN
    int v[NBLK][4];
    bool ok = base < NN;
    #pragma unroll
    for (int k = 0; k < NBLK; k++){
        int4 a = make_int4(0,0,0,0);
        if (ok) a = *(const int4*)(g_pc + (t*NBLK + k)*NN + base);
        v[k][0]=a.x; v[k][1]=a.y; v[k][2]=a.z; v[k][3]=a.w;
    }
    int cnt[4];
    int tsum = 0;
    #pragma unroll
    for (int e = 0; e < 4; e++){
        int run = 0;
        #pragma unroll
        for (int k = 0; k < NBLK; k++){
            int tmp = v[k][e];
            v[k][e] = run;                  // exclusive prefix across blocks
            run += tmp;
        }
        cnt[e] = run;
        tsum += run;
    }
    if (ok){
        #pragma unroll
        for (int k = 0; k < NBLK; k++)
            *(int4*)(g_pc + (t*NBLK + k)*NN + base) =
                make_int4(v[k][0], v[k][1], v[k][2], v[k][3]);
        *(int4*)(g_cnt + t*NN + base) = make_int4(cnt[0], cnt[1], cnt[2], cnt[3]);
    }
    sd[tid] = tsum;
    __syncthreads();
    #pragma unroll
    for (int ofs = 128; ofs > 0; ofs >>= 1){
        if (tid < ofs) sd[tid] += sd[tid+ofs];
        __syncthreads();
    }
    if (tid == 0) g_bsum[b] = sd[0];
}

// ---------------- scan: per-chunk exclusive scan -> g_off (bbase inline) -------
__global__ void __launch_bounds__(256) scanC_kernel(){
    __shared__ int sd[256];
    __shared__ int bb;
    int b = blockIdx.x;
    int t = b / NCHK, chunk = b % NCHK;
    int tid = threadIdx.x;
    if (tid == 0){
        int run = 0;
        for (int k = 0; k < 2*chunk; k++) run += g_bsum[t*NPCH + k];
        bb = run;
        if (chunk == 0) g_off[t*(NN+1)] = 0;
    }
    int base = chunk*CHUNK + tid*8;
    int c[8];
    int tsum = 0;
    bool ok = base < NN;
    {
        int4 a = make_int4(0,0,0,0), d = make_int4(0,0,0,0);
        if (ok){
            const int4* p = (const int4*)(g_cnt + t*NN + base);
            a = p[0]; d = p[1];
        }
        c[0]=a.x; c[1]=a.y; c[2]=a.z; c[3]=a.w;
        c[4]=d.x; c[5]=d.y; c[6]=d.z; c[7]=d.w;
        #pragma unroll
        for (int e = 0; e < 8; e++) tsum += c[e];
    }
    sd[tid] = tsum;
    __syncthreads();
    #pragma unroll
    for (int ofs = 1; ofs < 256; ofs <<= 1){
        int add = (tid >= ofs) ? sd[tid-ofs] : 0;
        __syncthreads();
        sd[tid] += add;
        __syncthreads();
    }
    int run = sd[tid] - tsum + bb;
    if (ok){
        #pragma unroll
        for (int e = 0; e < 8; e++){
            run += c[e];
            g_off[t*(NN+1) + base + e + 1] = run;
        }
    }
}

// ---------------- CSR: fill, atomic-free (smem cursor table + stored ranks) ----
__global__ void __launch_bounds__(1024) fill2_kernel(const int* __restrict__ edges){
    extern __shared__ int cur[];            // [NN] = 80 KB
    int b = blockIdx.x;
    int t = b >> 4, blk = b & 15;
    const int* offT = g_off + t*(NN+1);
    const int* pc = g_pc + b*NN;
    for (int i = threadIdx.x; i < NN; i += 1024) cur[i] = offT[i] + pc[i];
    __syncthreads();
    const int4* srcp = (const int4*)(edges + t*2*NE + blk*SL);
    const int4* dstp = (const int4*)(edges + t*2*NE + NE + blk*SL);
    const int4* rnkp = (const int4*)(g_rank + t*NE + blk*SL);
    int* colT = g_col + t*NE;
    for (int i = threadIdx.x; i < SL/8; i += 1024){
        int4 sA = srcp[2*i],  sB = srcp[2*i+1];
        int4 dA = dstp[2*i],  dB = dstp[2*i+1];
        int4 rA = rnkp[2*i],  rB = rnkp[2*i+1];
        int pA0 = cur[dA.x] + rA.x;
        int pA1 = cur[dA.y] + rA.y;
        int pA2 = cur[dA.z] + rA.z;
        int pA3 = cur[dA.w] + rA.w;
        int pB0 = cur[dB.x] + rB.x;
        int pB1 = cur[dB.y] + rB.y;
        int pB2 = cur[dB.z] + rB.z;
        int pB3 = cur[dB.w] + rB.w;
        colT[pA0] = sA.x;
        colT[pA1] = sA.y;
        colT[pA2] = sA.z;
        colT[pA3] = sA.w;
        colT[pB0] = sB.x;
        colT[pB1] = sB.y;
        colT[pB2] = sB.z;
        colT[pB3] = sB.w;
    }
}

// ---------------- fold attention weights + transpose W2 (merged) ----------------
__global__ void paramwt_kernel(const float* __restrict__ W1, const float* __restrict__ as1,
                               const float* __restrict__ ad1,
                               const float* __restrict__ W2, const float* __restrict__ as2,
                               const float* __restrict__ ad2){
    int i = blockIdx.x*blockDim.x + threadIdx.x;
    if (i >= NT*HID*HID) return;
    int t = i >> 10;
    int r = i & 1023;
    int f = r >> 5, j = r & 31;
    const float* wb = W2 + (t*HID + f)*128 + j;
    g_Wt[i] = make_float4(wb[0], wb[32], wb[64], wb[96]);
    if (j < 4){
        int h = j;
        float sa = 0.f, sd = 0.f;
        const float* wrow = W2 + (t*HID + f)*128 + h*32;
        const float* arow = as2 + (t*4 + h)*32;
        const float* drow = ad2 + (t*4 + h)*32;
        #pragma unroll
        for (int c = 0; c < 32; c++){ sa += wrow[c]*arow[c]; sd += wrow[c]*drow[c]; }
        ((float*)g_As2)[(t*HID + f)*4 + h] = sa;
        ((float*)g_Ad2)[(t*HID + f)*4 + h] = sd;
        if (f == 0){
            float s1 = 0.f, d1 = 0.f;
            const float* w1 = W1 + t*128 + h*32;
            const float* a1 = as1 + (t*4 + h)*32;
            const float* dd1 = ad1 + (t*4 + h)*32;
            #pragma unroll
            for (int c = 0; c < 32; c++){ s1 += w1[c]*a1[c]; d1 += w1[c]*dd1[c]; }
            ((float*)g_SA)[t*4 + h] = s1;
            ((float*)g_DA)[t*4 + h] = d1;
        }
    }
}

// ---------------- layer-1 edge aggregation: thread per (type,dst), 4-edge ILP ----
__global__ void l1_edge_kernel(const float* __restrict__ x){
    int i = blockIdx.x*blockDim.x + threadIdx.x;
    if (i >= NT*NN) return;
    int t = i / NN, n = i - t*NN;
    float4 SAv = g_SA[t];
    float4 DAv = g_DA[t];
    float SA[4] = {SAv.x, SAv.y, SAv.z, SAv.w};
    float DA[4] = {DAv.x, DAv.y, DAv.z, DAv.w};
    float xd = x[c_dst[t]*NN + n];
    float dsc[4];
    #pragma unroll
    for (int h = 0; h < 4; h++) dsc[h] = xd * DA[h];
    const float* xs = x + c_src[t]*NN;
    const int* col = g_col + t*NE;
    int beg = g_off[t*(NN+1) + n];
    int end = g_off[t*(NN+1) + n + 1];
    float den[4] = {0,0,0,0}, acc[4] = {0,0,0,0};
    int j = beg;
    for (; j + 3 < end; j += 4){         // 4 independent x gathers in flight
        int s0 = col[j], s1 = col[j+1], s2 = col[j+2], s3 = col[j+3];
        float x0 = xs[s0], x1 = xs[s1], x2 = xs[s2], x3 = xs[s3];
        #pragma unroll
        for (int h = 0; h < 4; h++){
            float p0 = __expf(lrelu(x0*SA[h] + dsc[h]));
            float p1 = __expf(lrelu(x1*SA[h] + dsc[h]));
            float p2 = __expf(lrelu(x2*SA[h] + dsc[h]));
            float p3 = __expf(lrelu(x3*SA[h] + dsc[h]));
            den[h] += (p0 + p1) + (p2 + p3);
            acc[h] += (p0*x0 + p1*x1) + (p2*x2 + p3*x3);
        }
    }
    for (; j < end; j++){
        int s = col[j];
        float xv = xs[s];
        #pragma unroll
        for (int h = 0; h < 4; h++){
            float p = __expf(lrelu(xv*SA[h] + dsc[h]));
            den[h] += p;
            acc[h] += p*xv;
        }
    }
    float4 z;
    z.x = den[0] > 0.f ? acc[0]/den[0] : 0.f;
    z.y = den[1] > 0.f ? acc[1]/den[1] : 0.f;
    z.z = den[2] > 0.f ? acc[2]/den[2] : 0.f;
    z.w = den[3] > 0.f ? acc[3]/den[3] : 0.f;
    g_za[t*NN + n] = z;
}

// ---------------- layer-1 combine + layer-2 scores (fused, warp per node) -------
__global__ void l1cs_kernel(const float* __restrict__ W1, const float* __restrict__ b1){
    int wg = blockIdx.x*8 + (threadIdx.x >> 5);
    if (wg >= NCH*NN) return;
    int lane = threadIdx.x & 31;
    int c = wg / NN, n = wg - c*NN;
    int j = lane;
    float v = 0.f;
    #pragma unroll
    for (int k = 0; k < 4; k++){
        int t = c_in[c][k];
        float4 za = g_za[t*NN + n];
        const float* w = W1 + t*128;
        float o = za.x*w[j] + za.y*w[32+j] + za.z*w[64+j] + za.w*w[96+j];
        v += o*0.25f + b1[t*HID + j];
    }
    v *= 0.25f;                       // hetero mean over 4 incoming types
    v = v > 0.f ? v : 0.f;
    g_y[c*NN*HID + n*HID + j] = v;
    #pragma unroll
    for (int k = 0; k < 4; k++){
        int ts = c_out[c][k];         // this node is src for these types
        float4 a = g_As2[ts*HID + j];
        float4 s = make_float4(v*a.x, v*a.y, v*a.z, v*a.w);
        int td = c_in[c][k];          // this node is dst for these types
        float4 bq = g_Ad2[td*HID + j];
        float4 d = make_float4(v*bq.x, v*bq.y, v*bq.z, v*bq.w);
        #pragma unroll
        for (int o2 = 16; o2; o2 >>= 1){
            s.x += __shfl_xor_sync(0xffffffffu, s.x, o2);
            s.y += __shfl_xor_sync(0xffffffffu, s.y, o2);
            s.z += __shfl_xor_sync(0xffffffffu, s.z, o2);
            s.w += __shfl_xor_sync(0xffffffffu, s.w, o2);
            d.x += __shfl_xor_sync(0xffffffffu, d.x, o2);
            d.y += __shfl_xor_sync(0xffffffffu, d.y, o2);
            d.z += __shfl_xor_sync(0xffffffffu, d.z, o2);
            d.w += __shfl_xor_sync(0xffffffffu, d.w, o2);
        }
        if (lane == 0){
            g_s2[ts*NN + n] = s;
            g_d2[td*NN + n] = d;
        }
    }
}

// ---------------- layer-2 fused: softmax + gather + block-GEMM epilogue ----------
__global__ void __launch_bounds__(1024) l2_gather_kernel(const float* __restrict__ b2,
                                                         float* __restrict__ out){
    extern __shared__ float smemf[];
    float4* zsm = (float4*)smemf;                 // [4][32n][32f] f4(h): 64 KB
    float4* wbA = (float4*)(smemf + 16384);       // [32 warps][CAP]:     32 KB
    int*    cbA = (int*)  (smemf + 24576);        // [32 warps][CAP]:      8 KB
    float*  psum = (float*)wbA;                   // reused in phase 2:   16 KB
    int c = blockIdx.y;
    int tid = threadIdx.x;
    int warp = tid >> 5, lane = tid & 31;
    int n = blockIdx.x*32 + warp;                 // grid.x = 625, exact cover
    float4* wb = wbA + warp*CAP;
    int* cb = cbA + warp*CAP;
    #pragma unroll
    for (int k = 0; k < 4; k++){
        int t = c_in[c][k];
        const float* ysrc = g_y + c_src[t]*NN*HID;
        const int* col = g_col + t*NE;
        const float4* s2 = g_s2 + t*NN;
        int beg = g_off[t*(NN+1) + n], end = g_off[t*(NN+1) + n + 1];
        int deg = end - beg;
        float4 dv = g_d2[t*NN + n];
        float d0 = 0.f, d1 = 0.f, d2 = 0.f, d3 = 0.f;
        unsigned long long a01 = 0ull, a23 = 0ull;
        unsigned long long b01 = 0ull, b23 = 0ull;
        if (deg <= CAP){
            for (int base = 0; base < deg; base += 32){
                int j = base + lane;
                if (j < deg){
                    int s = col[beg + j];
                    float4 sv = s2[s];
                    float4 p;
                    p.x = __expf(lrelu(sv.x + dv.x));
                    p.y = __expf(lrelu(sv.y + dv.y));
                    p.z = __expf(lrelu(sv.z + dv.z));
                    p.w = __expf(lrelu(sv.w + dv.w));
                    d0 += p.x; d1 += p.y; d2 += p.z; d3 += p.w;
                    wb[j] = p; cb[j] = s;
                }
            }
            __syncwarp();
            #pragma unroll
            for (int o = 16; o; o >>= 1){
                d0 += __shfl_xor_sync(0xffffffffu, d0, o);
                d1 += __shfl_xor_sync(0xffffffffu, d1, o);
                d2 += __shfl_xor_sync(0xffffffffu, d2, o);
                d3 += __shfl_xor_sync(0xffffffffu, d3, o);
            }
            int i = 0;
            for (; i + 3 < deg; i += 4){        // ILP4 on the y-row gather
                int s0 = cb[i], s1 = cb[i+1], s2i = cb[i+2], s3 = cb[i+3];
                float y0 = ysrc[s0*HID + lane];
                float y1 = ysrc[s1*HID + lane];
                float y2 = ysrc[s2i*HID + lane];
                float y3 = ysrc[s3*HID + lane];
                ulonglong2 pw0 = *(const ulonglong2*)(wb + i);
                ulonglong2 pw1 = *(const ulonglong2*)(wb + i + 1);
                ulonglong2 pw2 = *(const ulonglong2*)(wb + i + 2);
                ulonglong2 pw3 = *(const ulonglong2*)(wb + i + 3);
                unsigned long long y20 = pk2(y0, y0);
                unsigned long long y21 = pk2(y1, y1);
                unsigned long long y22 = pk2(y2, y2);
                unsigned long long y23 = pk2(y3, y3);
                fma2(a01, pw0.x, y20); fma2(a23, pw0.y, y20);
                fma2(b01, pw1.x, y21); fma2(b23, pw1.y, y21);
                fma2(a01, pw2.x, y22); fma2(a23, pw2.y, y22);
                fma2(b01, pw3.x, y23); fma2(b23, pw3.y, y23);
            }
            for (; i < deg; i++){
                ulonglong2 pw = *(const ulonglong2*)(wb + i);
                float yv = ysrc[cb[i]*HID + lane];
                unsigned long long y2 = pk2(yv, yv);
                fma2(a01, pw.x, y2); fma2(a23, pw.y, y2);
            }
            add2(a01, a01, b01);
            add2(a23, a23, b23);
            __syncwarp();
        } else {                                  // rare fallback: recompute path
            for (int base = beg; base < end; base += 32){
                int j = base + lane;
                if (j < end){
                    int s = col[j];
                    float4 sv = s2[s];
                    d0 += __expf(lrelu(sv.x + dv.x));
                    d1 += __expf(lrelu(sv.y + dv.y));
                    d2 += __expf(lrelu(sv.z + dv.z));
                    d3 += __expf(lrelu(sv.w + dv.w));
                }
            }
            #pragma unroll
            for (int o = 16; o; o >>= 1){
                d0 += __shfl_xor_sync(0xffffffffu, d0, o);
                d1 += __shfl_xor_sync(0xffffffffu, d1, o);
                d2 += __shfl_xor_sync(0xffffffffu, d2, o);
                d3 += __shfl_xor_sync(0xffffffffu, d3, o);
            }
            for (int base = beg; base < end; base += 32){
                int j = base + lane;
                int m = min(32, end - base);
                if (j < end){
                    int s = col[j];
                    float4 sv = s2[s];
                    float4 p;
                    p.x = __expf(lrelu(sv.x + dv.x));
                    p.y = __expf(lrelu(sv.y + dv.y));
                    p.z = __expf(lrelu(sv.z + dv.z));
                    p.w = __expf(lrelu(sv.w + dv.w));
                    wb[lane] = p; cb[lane] = s;
                }
                __syncwarp();
                for (int i = 0; i < m; i++){
                    ulonglong2 pw = *(const ulonglong2*)(wb + i);
                    float yv = ysrc[cb[i]*HID + lane];
                    unsigned long long y2 = pk2(yv, yv);
                    fma2(a01, pw.x, y2); fma2(a23, pw.y, y2);
                }
                __syncwarp();
            }
        }
        unsigned long long r01 = pk2(d0 > 0.f ? __fdividef(0.25f, d0) : 0.f,
                                     d1 > 0.f ? __fdividef(0.25f, d1) : 0.f);
        unsigned long long r23 = pk2(d2 > 0.f ? __fdividef(0.25f, d2) : 0.f,
                                     d3 > 0.f ? __fdividef(0.25f, d3) : 0.f);
        mul2(a01, a01, r01);
        mul2(a23, a23, r23);
        *(ulonglong2*)(zsm + (k*32 + warp)*32 + lane) = make_ulonglong2(a01, a23);
    }
    __syncthreads();
    // phase 2: block GEMM, 2x2 tiles, k split over thread groups; Wt from L1
    {
        int g  = tid >> 8;            // k
        int r  = tid & 255;
        int tn = r >> 4;              // 0..15
        int tj = r & 15;              // 0..15
        const float4* Zk = zsm + g*1024;
        const float4* Wk = g_Wt + c_in[c][g]*1024;
        unsigned long long aA00=0ull, aB00=0ull, aA01=0ull, aB01=0ull;
        unsigned long long aA10=0ull, aB10=0ull, aA11=0ull, aB11=0ull;
        #pragma unroll 4
        for (int f = 0; f < 32; f++){
            ulonglong2 z0 = *(const ulonglong2*)(Zk + tn*32 + f);
            ulonglong2 z1 = *(const ulonglong2*)(Zk + (tn+16)*32 + f);
            ulonglong2 w0 = *(const ulonglong2*)(Wk + f*32 + tj);
            ulonglong2 w1 = *(const ulonglong2*)(Wk + f*32 + tj + 16);
            fma2(aA00, z0.x, w0.x); fma2(aB00, z0.y, w0.y);
            fma2(aA01, z0.x, w1.x); fma2(aB01, z0.y, w1.y);
            fma2(aA10, z1.x, w0.x); fma2(aB10, z1.y, w0.y);
            fma2(aA11, z1.x, w1.x); fma2(aB11, z1.y, w1.y);
        }
        float2 A, B;
        A = upk2(aA00); B = upk2(aB00);
        psum[(g*32 + tn   )*32 + tj   ] = A.x + A.y + B.x + B.y;
        A = upk2(aA01); B = upk2(aB01);
        psum[(g*32 + tn   )*32 + tj+16] = A.x + A.y + B.x + B.y;
        A = upk2(aA10); B = upk2(aB10);
        psum[(g*32 + tn+16)*32 + tj   ] = A.x + A.y + B.x + B.y;
        A = upk2(aA11); B = upk2(aB11);
        psum[(g*32 + tn+16)*32 + tj+16] = A.x + A.y + B.x + B.y;
    }
    __syncthreads();
    {
        int nn = tid >> 5, j = tid & 31;
        float o = psum[nn*32 + j] + psum[1024 + nn*32 + j]
                + psum[2048 + nn*32 + j] + psum[3072 + nn*32 + j];
        float bs = b2[c_in[c][0]*HID + j] + b2[c_in[c][1]*HID + j]
                 + b2[c_in[c][2]*HID + j] + b2[c_in[c][3]*HID + j];
        float v = (o + bs)*0.25f;     // hetero mean over 4 types
        int ng = blockIdx.x*32 + nn;
        out[ng*(NCH*HID) + c*HID + j] = v > 0.f ? v : 0.f;
    }
}

extern "C" void kernel_launch(void* const* d_in, const int* in_sizes, int n_in,
                              void* d_out, int out_size){
    const float* x   = (const float*)d_in[0];
    const int*   edg = (const int*)  d_in[1];
    const float* W1  = (const float*)d_in[2];
    const float* as1 = (const float*)d_in[3];
    const float* ad1 = (const float*)d_in[4];
    const float* b1  = (const float*)d_in[5];
    const float* W2  = (const float*)d_in[6];
    const float* as2 = (const float*)d_in[7];
    const float* ad2 = (const float*)d_in[8];
    const float* b2  = (const float*)d_in[9];
    float* out = (float*)d_out;

    static bool attr_set = false;
    if (!attr_set){
        cudaFuncSetAttribute(l2_gather_kernel,
                             cudaFuncAttributeMaxDynamicSharedMemorySize, 106496);
        cudaFuncSetAttribute(countrank_kernel,
                             cudaFuncAttributeMaxDynamicSharedMemorySize, NN*4);
        cudaFuncSetAttribute(fill2_kernel,
                             cudaFuncAttributeMaxDynamicSharedMemorySize, NN*4);
        attr_set = true;
    }

    countrank_kernel<<<NT*NBLK, 1024, NN*4>>>(edg);   // idx 0
    prefA_kernel<<<NT*NPCH, 256>>>();                 // idx 1
    scanC_kernel<<<NT*NCHK, 256>>>();                 // idx 2
    fill2_kernel<<<NT*NBLK, 1024, NN*4>>>(edg);       // idx 3  <- profiler window
    paramwt_kernel<<<(NT*HID*HID + 255)/256, 256>>>(W1, as1, ad1, W2, as2, ad2);
    l1_edge_kernel<<<(NT*NN + 255)/256, 256>>>(x);
    l1cs_kernel<<<(NCH*NN + 7)/8, 256>>>(W1, b1);
    dim3 g2(NN/32, NCH);   // 625 x 4
    l2_gather_kernel<<<g2, 1024, 106496>>>(b2, out);
}